// round 2
// baseline (speedup 1.0000x reference)
#include <cuda_runtime.h>
#include <math.h>

#define NEDGE 524288
#define NNODE 32768
#define NGR   8
#define NLOC  4096
#define FIN   128
#define HID   512

// ---- output layout (tuple flattened): ----
// [0,80)        log_softmax logits (8x10)
// [80]          mc_loss
// [81]          o_loss
// [82,65618)    s_logits (32768x2)
// [65618,65650) out_adj (8x2x2, normalized)
#define OUT_MC    80
#define OUT_OL    81
#define OUT_SLOG  82
#define OUT_OA    65618

// ---- scratch (static device globals; no allocation allowed) ----
__device__ float g_agg[NNODE * FIN];       // 16 MB
__device__ float g_h[NNODE * HID];         // 64 MB
__device__ float g_s[NNODE * 2];
__device__ int   g_cnt[NNODE + 1];
__device__ int   g_offs[NNODE + 1];
__device__ int   g_cursor[NNODE];
__device__ int   g_ssrc[NEDGE];
__device__ float g_sw[NEDGE];
__device__ float g_d[NNODE];               // degree by src (adj row sums)
__device__ float g_accum[NGR * 4];         // ss00, ss01, ss11, mincut_den
__device__ float g_oaraw[NGR * 4];         // raw out_adj [c][k]
__device__ float g_oan[NGR * 4];           // normalized out_adj
__device__ float g_out[NGR * 2 * HID];     // pooled features
__device__ float g_xm[NGR * HID];
__device__ float g_h2[NGR * HID];

__device__ __forceinline__ float wred(float v) {
#pragma unroll
    for (int o = 16; o; o >>= 1) v += __shfl_down_sync(0xffffffffu, v, o);
    return v;
}

// ---------------- zero scratch ----------------
__global__ void zero_kernel() {
    int i = blockIdx.x * 256 + threadIdx.x;
    if (i < NNODE + 1) g_cnt[i] = 0;
    if (i < NNODE)     g_d[i] = 0.f;
    if (i < NGR * 2 * HID) g_out[i] = 0.f;
    if (i < NGR * 4) { g_accum[i] = 0.f; g_oaraw[i] = 0.f; }
}

// ---------------- count by dst + degree by src ----------------
__global__ void count_kernel(const int* __restrict__ ei,
                             const float* __restrict__ ew) {
    int e = blockIdx.x * 256 + threadIdx.x;
    if (e >= NEDGE) return;
    int src = ei[e];
    int dst = ei[NEDGE + e];
    atomicAdd(&g_cnt[dst], 1);
    atomicAdd(&g_d[src], ew[e]);
}

// ---------------- exclusive scan over 32768 counts (1 block, 1024 thr) ----
__global__ void scan_kernel() {
    __shared__ int sm[1024];
    int tid = threadIdx.x;
    int base = tid * 32;
    int sum = 0;
#pragma unroll
    for (int i = 0; i < 32; i++) sum += g_cnt[base + i];
    sm[tid] = sum;
    __syncthreads();
    for (int o = 1; o < 1024; o <<= 1) {
        int v = (tid >= o) ? sm[tid - o] : 0;
        __syncthreads();
        sm[tid] += v;
        __syncthreads();
    }
    int run = sm[tid] - sum;   // exclusive prefix
#pragma unroll
    for (int i = 0; i < 32; i++) {
        int c = g_cnt[base + i];
        g_offs[base + i] = run;
        g_cursor[base + i] = run;
        run += c;
    }
    if (tid == 1023) g_offs[NNODE] = run;
}

// ---------------- scatter edges sorted by dst ----------------
__global__ void scatter_kernel(const int* __restrict__ ei,
                               const float* __restrict__ ew) {
    int e = blockIdx.x * 256 + threadIdx.x;
    if (e >= NEDGE) return;
    int src = ei[e];
    int dst = ei[NEDGE + e];
    int pos = atomicAdd(&g_cursor[dst], 1);
    g_ssrc[pos] = src;
    g_sw[pos]   = ew[e];
}

// ---------------- agg[dst] = sum w * x[src]  (warp per dst node) --------
__global__ void agg_kernel(const float* __restrict__ x) {
    int gwarp = (blockIdx.x * 256 + threadIdx.x) >> 5;   // 0..32767
    int lane  = threadIdx.x & 31;
    int s0 = g_offs[gwarp], s1 = g_offs[gwarp + 1];
    const float4* x4 = (const float4*)x;
    float4 acc = make_float4(0.f, 0.f, 0.f, 0.f);
    for (int e = s0; e < s1; e++) {
        int sn = g_ssrc[e];
        float w = g_sw[e];
        float4 v = x4[sn * 32 + lane];
        acc.x += w * v.x; acc.y += w * v.y; acc.z += w * v.z; acc.w += w * v.w;
    }
    ((float4*)g_agg)[gwarp * 32 + lane] = acc;
}

// ---------------- h = relu(agg@W1 + x@W2 + b)  tiled fp32 GEMM ----------
#define GBM 128
#define GBN 128
#define GBK 16
__global__ __launch_bounds__(256) void gemm_h_kernel(const float* __restrict__ x,
                                                     const float* __restrict__ W1,
                                                     const float* __restrict__ W2,
                                                     const float* __restrict__ bias) {
    __shared__ float As[GBK][GBM];
    __shared__ float Bs[GBK][GBN];
    int bm = blockIdx.x * GBM;
    int bn = blockIdx.y * GBN;
    int tid = threadIdx.x;
    int ty = tid >> 4, tx = tid & 15;
    float acc[8][8];
#pragma unroll
    for (int i = 0; i < 8; i++)
#pragma unroll
        for (int j = 0; j < 8; j++) acc[i][j] = 0.f;

    for (int p = 0; p < 2; p++) {
        const float* A = p ? x : g_agg;          // [32768, 128]
        const float* B = p ? W2 : W1;            // [128, 512]
        for (int k0 = 0; k0 < FIN; k0 += GBK) {
#pragma unroll
            for (int t = 0; t < 8; t++) {
                int i = tid + t * 256;
                int r = i >> 4, c = i & 15;
                As[c][r] = A[(bm + r) * FIN + k0 + c];
            }
#pragma unroll
            for (int t = 0; t < 8; t++) {
                int i = tid + t * 256;
                int r = i >> 7, c = i & 127;
                Bs[r][c] = B[(k0 + r) * HID + bn + c];
            }
            __syncthreads();
#pragma unroll
            for (int k = 0; k < GBK; k++) {
                float a[8], b[8];
#pragma unroll
                for (int i = 0; i < 8; i++) a[i] = As[k][ty * 8 + i];
#pragma unroll
                for (int j = 0; j < 8; j++) b[j] = Bs[k][tx * 8 + j];
#pragma unroll
                for (int i = 0; i < 8; i++)
#pragma unroll
                    for (int j = 0; j < 8; j++) acc[i][j] += a[i] * b[j];
            }
            __syncthreads();
        }
    }
#pragma unroll
    for (int i = 0; i < 8; i++) {
        int row = bm + ty * 8 + i;
#pragma unroll
        for (int j = 0; j < 8; j++) {
            int col = bn + tx * 8 + j;
            float v = acc[i][j] + bias[col];
            g_h[row * HID + col] = fmaxf(v, 0.f);
        }
    }
}

// ---------------- s_logits, softmax s, per-graph ss/den accumulation ----
__global__ void s_kernel(const float* __restrict__ Wp,
                         const float* __restrict__ bp,
                         float* __restrict__ dout) {
    __shared__ float red[8][4];
    int wip = threadIdx.x >> 5;
    int lane = threadIdx.x & 31;
    int node = blockIdx.x * 8 + wip;
    const float* hrow = g_h + (size_t)node * HID;
    float d0 = 0.f, d1 = 0.f;
    for (int k = lane; k < HID; k += 32) {
        float hv = hrow[k];
        d0 += hv * Wp[k * 2];
        d1 += hv * Wp[k * 2 + 1];
    }
    d0 = wred(d0); d1 = wred(d1);
    if (lane == 0) {
        d0 += bp[0]; d1 += bp[1];
        dout[OUT_SLOG + node * 2]     = d0;
        dout[OUT_SLOG + node * 2 + 1] = d1;
        float m = fmaxf(d0, d1);
        float e0 = expf(d0 - m), e1 = expf(d1 - m);
        float inv = 1.f / (e0 + e1);
        float s0 = e0 * inv, s1 = e1 * inv;
        g_s[node * 2] = s0; g_s[node * 2 + 1] = s1;
        float dn = g_d[node];
        red[wip][0] = s0 * s0;
        red[wip][1] = s0 * s1;
        red[wip][2] = s1 * s1;
        red[wip][3] = dn * (s0 * s0 + s1 * s1);
    }
    __syncthreads();
    if (threadIdx.x < 4) {
        int b = node >> 12;   // 4096 nodes per graph; all warps in block same graph
        float t = 0.f;
#pragma unroll
        for (int w = 0; w < 8; w++) t += red[w][threadIdx.x];
        atomicAdd(&g_accum[b * 4 + threadIdx.x], t);
    }
}

// ---------------- out[b,c,f] = sum_n s[n,c]*h[n,f] ----------------------
__global__ void pool_kernel() {
    int b = blockIdx.x;
    int f = blockIdx.y * 128 + threadIdx.x;
    int ns = blockIdx.z;
    int nb = b * NLOC + ns * 512;
    float a0 = 0.f, a1 = 0.f;
    for (int n = 0; n < 512; n++) {
        int node = nb + n;
        float hv = g_h[(size_t)node * HID + f];
        a0 += g_s[node * 2] * hv;
        a1 += g_s[node * 2 + 1] * hv;
    }
    atomicAdd(&g_out[(b * 2 + 0) * HID + f], a0);
    atomicAdd(&g_out[(b * 2 + 1) * HID + f], a1);
}

// ---------------- out_adj[b,c,k] = sum_e s[src,c]*w*s[dst,k] ------------
__global__ void oa_kernel(const int* __restrict__ ei,
                          const float* __restrict__ ew) {
    __shared__ float red[8][4];
    int e = blockIdx.x * 256 + threadIdx.x;
    int src = ei[e];
    int dst = ei[NEDGE + e];
    float w = ew[e];
    float ss0 = g_s[src * 2], ss1 = g_s[src * 2 + 1];
    float sd0 = g_s[dst * 2], sd1 = g_s[dst * 2 + 1];
    float v00 = ss0 * w * sd0, v01 = ss0 * w * sd1;
    float v10 = ss1 * w * sd0, v11 = ss1 * w * sd1;
    v00 = wred(v00); v01 = wred(v01); v10 = wred(v10); v11 = wred(v11);
    int wip = threadIdx.x >> 5;
    if ((threadIdx.x & 31) == 0) {
        red[wip][0] = v00; red[wip][1] = v01; red[wip][2] = v10; red[wip][3] = v11;
    }
    __syncthreads();
    if (threadIdx.x < 4) {
        int b = src >> 12;   // 65536 edges per graph, blocks aligned -> same b
        float t = 0.f;
#pragma unroll
        for (int w2 = 0; w2 < 8; w2++) t += red[w2][threadIdx.x];
        atomicAdd(&g_oaraw[b * 4 + threadIdx.x], t);
    }
}

// ---------------- per-graph losses + out_adj normalization --------------
__global__ void finalize_kernel(float* __restrict__ dout) {
    int b = threadIdx.x;   // 32 threads, 8 active
    float mc = 0.f, ol = 0.f;
    if (b < NGR) {
        float a00 = g_oaraw[b * 4 + 0], a01 = g_oaraw[b * 4 + 1];
        float a10 = g_oaraw[b * 4 + 2], a11 = g_oaraw[b * 4 + 3];
        float num = a00 + a11;
        float den = g_accum[b * 4 + 3];
        mc = -(num / den);
        float ss00 = g_accum[b * 4 + 0], ss01 = g_accum[b * 4 + 1], ss11 = g_accum[b * 4 + 2];
        float nrm = sqrtf(ss00 * ss00 + 2.f * ss01 * ss01 + ss11 * ss11);
        const float q = 0.70710678118654752f;
        float n00 = ss00 / nrm - q, n01 = ss01 / nrm, n11 = ss11 / nrm - q;
        ol = sqrtf(n00 * n00 + 2.f * n01 * n01 + n11 * n11);
        // zero diag + symmetric degree normalization
        float d2_0 = sqrtf(a01) + 1e-15f;
        float d2_1 = sqrtf(a10) + 1e-15f;
        float oa01 = a01 / (d2_0 * d2_1);
        float oa10 = a10 / (d2_1 * d2_0);
        g_oan[b * 4 + 0] = 0.f; g_oan[b * 4 + 1] = oa01;
        g_oan[b * 4 + 2] = oa10; g_oan[b * 4 + 3] = 0.f;
        dout[OUT_OA + b * 4 + 0] = 0.f;
        dout[OUT_OA + b * 4 + 1] = oa01;
        dout[OUT_OA + b * 4 + 2] = oa10;
        dout[OUT_OA + b * 4 + 3] = 0.f;
    }
    mc = wred(mc); ol = wred(ol);
    if (threadIdx.x == 0) {
        dout[OUT_MC] = mc / (float)NGR;
        dout[OUT_OL] = ol / (float)NGR;
    }
}

// ---------------- xm = mean_c(agg3@W_rel3 + b + out@W_root3) ------------
__global__ void xm_kernel(const float* __restrict__ Wrel3,
                          const float* __restrict__ brel3,
                          const float* __restrict__ Wroot3) {
    int b = blockIdx.x >> 1;
    int f = ((blockIdx.x & 1) << 8) + threadIdx.x;
    float oa01 = g_oan[b * 4 + 1], oa10 = g_oan[b * 4 + 2];
    const float* o0 = &g_out[(b * 2 + 0) * HID];
    const float* o1 = &g_out[(b * 2 + 1) * HID];
    float acc = 0.f;
    for (int k = 0; k < HID; k++) {
        float u = oa10 * o1[k] + oa01 * o0[k];   // agg3[b,0,k] + agg3[b,1,k]
        float v = o0[k] + o1[k];
        acc += u * Wrel3[k * HID + f] + v * Wroot3[k * HID + f];
    }
    g_xm[b * HID + f] = 0.5f * acc + brel3[f];
}

// ---------------- h2 = relu(xm @ W_lin1 + b) ----------------------------
__global__ void h2_kernel(const float* __restrict__ Wlin1,
                          const float* __restrict__ blin1) {
    int b = blockIdx.x >> 1;
    int f = ((blockIdx.x & 1) << 8) + threadIdx.x;
    float acc = 0.f;
    for (int k = 0; k < HID; k++)
        acc += g_xm[b * HID + k] * Wlin1[k * HID + f];
    g_h2[b * HID + f] = fmaxf(acc + blin1[f], 0.f);
}

// ---------------- logits + log_softmax ----------------------------------
__global__ void logits_kernel(const float* __restrict__ Wlin2,
                              const float* __restrict__ blin2,
                              float* __restrict__ dout) {
    __shared__ float lg[10];
    int b = blockIdx.x;
    int o = threadIdx.x >> 5;     // 10 warps
    int lane = threadIdx.x & 31;
    float acc = 0.f;
    for (int k = lane; k < HID; k += 32)
        acc += g_h2[b * HID + k] * Wlin2[k * 10 + o];
    acc = wred(acc);
    if (lane == 0) lg[o] = acc + blin2[o];
    __syncthreads();
    if (threadIdx.x == 0) {
        float m = lg[0];
#pragma unroll
        for (int i = 1; i < 10; i++) m = fmaxf(m, lg[i]);
        float s = 0.f;
#pragma unroll
        for (int i = 0; i < 10; i++) s += expf(lg[i] - m);
        float lse = logf(s) + m;
#pragma unroll
        for (int i = 0; i < 10; i++) dout[b * 10 + i] = lg[i] - lse;
    }
}

extern "C" void kernel_launch(void* const* d_in, const int* in_sizes, int n_in,
                              void* d_out, int out_size) {
    const float* x       = (const float*)d_in[0];
    const int*   ei      = (const int*)d_in[1];   // int32! (JAX x64 disabled)
    // d_in[2] = batch (int32, derivable from node index, unused)
    const float* ew      = (const float*)d_in[3];
    const float* W_rel1  = (const float*)d_in[4];
    const float* b_rel1  = (const float*)d_in[5];
    const float* W_root1 = (const float*)d_in[6];
    const float* W_pool  = (const float*)d_in[7];
    const float* b_pool  = (const float*)d_in[8];
    const float* W_rel3  = (const float*)d_in[9];
    const float* b_rel3  = (const float*)d_in[10];
    const float* W_root3 = (const float*)d_in[11];
    const float* W_lin1  = (const float*)d_in[12];
    const float* b_lin1  = (const float*)d_in[13];
    const float* W_lin2  = (const float*)d_in[14];
    const float* b_lin2  = (const float*)d_in[15];
    float* out = (float*)d_out;

    zero_kernel<<<129, 256>>>();
    count_kernel<<<NEDGE / 256, 256>>>(ei, ew);
    scan_kernel<<<1, 1024>>>();
    scatter_kernel<<<NEDGE / 256, 256>>>(ei, ew);
    agg_kernel<<<NNODE / 8, 256>>>(x);
    gemm_h_kernel<<<dim3(NNODE / GBM, HID / GBN), 256>>>(x, W_rel1, W_root1, b_rel1);
    s_kernel<<<NNODE / 8, 256>>>(W_pool, b_pool, out);
    pool_kernel<<<dim3(NGR, 4, 8), 128>>>();
    oa_kernel<<<NEDGE / 256, 256>>>(ei, ew);
    finalize_kernel<<<1, 32>>>(out);
    xm_kernel<<<16, 256>>>(W_rel3, b_rel3, W_root3);
    h2_kernel<<<16, 256>>>(W_lin1, b_lin1);
    logits_kernel<<<8, 320>>>(W_lin2, b_lin2, out);
}

// round 3
// speedup vs baseline: 1.1596x; 1.1596x over previous
#include <cuda_runtime.h>
#include <math.h>
#include <stdint.h>

#define NEDGE 524288
#define NNODE 32768
#define NGR   8
#define NLOC  4096
#define FIN   128
#define HID   512

// ---- output layout (tuple flattened): ----
#define OUT_MC    80
#define OUT_OL    81
#define OUT_SLOG  82
#define OUT_OA    65618

// ---- scratch ----
__device__ float g_agg[NNODE * FIN];
__device__ float g_h[NNODE * HID];
__device__ float g_s[NNODE * 2];
__device__ int   g_cnt[NNODE + 1];
__device__ int   g_offs[NNODE + 1];
__device__ int   g_cursor[NNODE];
__device__ int   g_ssrc[NEDGE];
__device__ float g_sw[NEDGE];
__device__ float g_d[NNODE];
__device__ float g_accum[NGR * 4];
__device__ float g_oaraw[NGR * 4];
__device__ float g_oan[NGR * 4];
__device__ float g_out[NGR * 2 * HID];
__device__ float g_xm[NGR * HID];
__device__ float g_h2[NGR * HID];

__device__ __forceinline__ float wred(float v) {
#pragma unroll
    for (int o = 16; o; o >>= 1) v += __shfl_down_sync(0xffffffffu, v, o);
    return v;
}

__device__ __forceinline__ void cvt_hilo(float v, float& hi, float& lo) {
    uint32_t u;
    asm("cvt.rna.tf32.f32 %0, %1;" : "=r"(u) : "f"(v));
    hi = __uint_as_float(u);
    float rem = v - hi;
    uint32_t u2;
    asm("cvt.rna.tf32.f32 %0, %1;" : "=r"(u2) : "f"(rem));
    lo = __uint_as_float(u2);
}

#define MMA_TF32(d, a0, a1, a2, a3, b0, b1)                                   \
    asm volatile(                                                             \
        "mma.sync.aligned.m16n8k8.row.col.f32.tf32.tf32.f32 "                 \
        "{%0,%1,%2,%3},{%4,%5,%6,%7},{%8,%9},{%0,%1,%2,%3};"                  \
        : "+f"(d[0]), "+f"(d[1]), "+f"(d[2]), "+f"(d[3])                      \
        : "r"(__float_as_uint(a0)), "r"(__float_as_uint(a1)),                 \
          "r"(__float_as_uint(a2)), "r"(__float_as_uint(a3)),                 \
          "r"(__float_as_uint(b0)), "r"(__float_as_uint(b1)))

// ---------------- zero scratch ----------------
__global__ void zero_kernel() {
    int i = blockIdx.x * 256 + threadIdx.x;
    if (i < NNODE + 1) g_cnt[i] = 0;
    if (i < NNODE)     g_d[i] = 0.f;
    if (i < NGR * 2 * HID) g_out[i] = 0.f;
    if (i < NGR * 4) { g_accum[i] = 0.f; g_oaraw[i] = 0.f; }
}

// ---------------- count by dst + degree by src ----------------
__global__ void count_kernel(const int* __restrict__ ei,
                             const float* __restrict__ ew) {
    int e = blockIdx.x * 256 + threadIdx.x;
    if (e >= NEDGE) return;
    int src = ei[e];
    int dst = ei[NEDGE + e];
    atomicAdd(&g_cnt[dst], 1);
    atomicAdd(&g_d[src], ew[e]);
}

// ---------------- exclusive scan (1 block, 1024 thr) ----------------
__global__ void scan_kernel() {
    __shared__ int sm[1024];
    int tid = threadIdx.x;
    int base = tid * 32;
    int sum = 0;
#pragma unroll
    for (int i = 0; i < 32; i++) sum += g_cnt[base + i];
    sm[tid] = sum;
    __syncthreads();
    for (int o = 1; o < 1024; o <<= 1) {
        int v = (tid >= o) ? sm[tid - o] : 0;
        __syncthreads();
        sm[tid] += v;
        __syncthreads();
    }
    int run = sm[tid] - sum;
#pragma unroll
    for (int i = 0; i < 32; i++) {
        int c = g_cnt[base + i];
        g_offs[base + i] = run;
        g_cursor[base + i] = run;
        run += c;
    }
    if (tid == 1023) g_offs[NNODE] = run;
}

// ---------------- scatter edges sorted by dst ----------------
__global__ void scatter_kernel(const int* __restrict__ ei,
                               const float* __restrict__ ew) {
    int e = blockIdx.x * 256 + threadIdx.x;
    if (e >= NEDGE) return;
    int src = ei[e];
    int dst = ei[NEDGE + e];
    int pos = atomicAdd(&g_cursor[dst], 1);
    g_ssrc[pos] = src;
    g_sw[pos]   = ew[e];
}

// ---------------- agg[dst] = sum w * x[src]  (warp per dst) ------------
__global__ void agg_kernel(const float* __restrict__ x) {
    int gwarp = (blockIdx.x * 256 + threadIdx.x) >> 5;
    int lane  = threadIdx.x & 31;
    int s0 = g_offs[gwarp], s1 = g_offs[gwarp + 1];
    const float4* x4 = (const float4*)x;
    float4 acc = make_float4(0.f, 0.f, 0.f, 0.f);
    for (int e = s0; e < s1; e++) {
        int sn = g_ssrc[e];
        float w = g_sw[e];
        float4 v = x4[sn * 32 + lane];
        acc.x += w * v.x; acc.y += w * v.y; acc.z += w * v.z; acc.w += w * v.w;
    }
    ((float4*)g_agg)[gwarp * 32 + lane] = acc;
}

// ---------------- h = relu([agg|x] @ [W1;W2] + b)  3xTF32 tensor GEMM ----
// Block tile 128x128, K=256 consumed in 16 stages of BK=16.
// 8 warps: warp_m = wid&1 (64 rows), warp_n = wid>>1 (32 cols).
#define APAD 20
#define BPAD 136
__global__ __launch_bounds__(256) void gemm_h_tc(const float* __restrict__ x,
                                                 const float* __restrict__ W1,
                                                 const float* __restrict__ W2,
                                                 const float* __restrict__ bias) {
    __shared__ float As_hi[128][APAD], As_lo[128][APAD];
    __shared__ float Bs_hi[16][BPAD],  Bs_lo[16][BPAD];

    int tid  = threadIdx.x;
    int lane = tid & 31;
    int wid  = tid >> 5;
    int warp_m = wid & 1;
    int warp_n = wid >> 1;
    int bm = blockIdx.x * 128;
    int bn = blockIdx.y * 128;

    float cacc[4][4][4];
#pragma unroll
    for (int i = 0; i < 4; i++)
#pragma unroll
        for (int j = 0; j < 4; j++)
#pragma unroll
            for (int r = 0; r < 4; r++) cacc[i][j][r] = 0.f;

    for (int kt = 0; kt < 16; kt++) {
        int p  = kt >> 3;
        int k0 = (kt & 7) * 16;
        const float* A = p ? x : g_agg;    // [32768,128]
        const float* B = p ? W2 : W1;      // [128,512]

        // load A tile: 128 rows x 16 cols
#pragma unroll
        for (int t = 0; t < 2; t++) {
            int i  = tid + t * 256;       // 0..511
            int r  = i >> 2;              // row 0..127
            int c4 = (i & 3) * 4;         // 0,4,8,12
            float4 v = *(const float4*)&A[(size_t)(bm + r) * FIN + k0 + c4];
            float hi, lo;
            cvt_hilo(v.x, hi, lo); As_hi[r][c4 + 0] = hi; As_lo[r][c4 + 0] = lo;
            cvt_hilo(v.y, hi, lo); As_hi[r][c4 + 1] = hi; As_lo[r][c4 + 1] = lo;
            cvt_hilo(v.z, hi, lo); As_hi[r][c4 + 2] = hi; As_lo[r][c4 + 2] = lo;
            cvt_hilo(v.w, hi, lo); As_hi[r][c4 + 3] = hi; As_lo[r][c4 + 3] = lo;
        }
        // load B tile: 16 rows x 128 cols
#pragma unroll
        for (int t = 0; t < 2; t++) {
            int i  = tid + t * 256;
            int r  = i >> 5;              // 0..15
            int c4 = (i & 31) * 4;        // 0..124
            float4 v = *(const float4*)&B[(size_t)(k0 + r) * HID + bn + c4];
            float4 vh, vl;
            cvt_hilo(v.x, vh.x, vl.x);
            cvt_hilo(v.y, vh.y, vl.y);
            cvt_hilo(v.z, vh.z, vl.z);
            cvt_hilo(v.w, vh.w, vl.w);
            *(float4*)&Bs_hi[r][c4] = vh;
            *(float4*)&Bs_lo[r][c4] = vl;
        }
        __syncthreads();

#pragma unroll
        for (int k8 = 0; k8 < 2; k8++) {
            int kb = k8 * 8;
            float a_hi[4][4], a_lo[4][4];
#pragma unroll
            for (int mi = 0; mi < 4; mi++) {
                int row = warp_m * 64 + mi * 16 + (lane >> 2);
                int col = kb + (lane & 3);
                a_hi[mi][0] = As_hi[row][col];
                a_hi[mi][1] = As_hi[row + 8][col];
                a_hi[mi][2] = As_hi[row][col + 4];
                a_hi[mi][3] = As_hi[row + 8][col + 4];
                a_lo[mi][0] = As_lo[row][col];
                a_lo[mi][1] = As_lo[row + 8][col];
                a_lo[mi][2] = As_lo[row][col + 4];
                a_lo[mi][3] = As_lo[row + 8][col + 4];
            }
#pragma unroll
            for (int ni = 0; ni < 4; ni++) {
                int ncol = warp_n * 32 + ni * 8 + (lane >> 2);
                int krow = kb + (lane & 3);
                float b_hi0 = Bs_hi[krow][ncol];
                float b_hi1 = Bs_hi[krow + 4][ncol];
                float b_lo0 = Bs_lo[krow][ncol];
                float b_lo1 = Bs_lo[krow + 4][ncol];
#pragma unroll
                for (int mi = 0; mi < 4; mi++) {
                    MMA_TF32(cacc[mi][ni], a_hi[mi][0], a_hi[mi][1], a_hi[mi][2], a_hi[mi][3], b_hi0, b_hi1);
                    MMA_TF32(cacc[mi][ni], a_lo[mi][0], a_lo[mi][1], a_lo[mi][2], a_lo[mi][3], b_hi0, b_hi1);
                    MMA_TF32(cacc[mi][ni], a_hi[mi][0], a_hi[mi][1], a_hi[mi][2], a_hi[mi][3], b_lo0, b_lo1);
                }
            }
        }
        __syncthreads();
    }

    // epilogue: bias + relu, write g_h
#pragma unroll
    for (int mi = 0; mi < 4; mi++) {
        int row0 = bm + warp_m * 64 + mi * 16 + (lane >> 2);
#pragma unroll
        for (int ni = 0; ni < 4; ni++) {
            int col = bn + warp_n * 32 + ni * 8 + 2 * (lane & 3);
            float b0 = bias[col], b1 = bias[col + 1];
            float2 v0, v1;
            v0.x = fmaxf(cacc[mi][ni][0] + b0, 0.f);
            v0.y = fmaxf(cacc[mi][ni][1] + b1, 0.f);
            v1.x = fmaxf(cacc[mi][ni][2] + b0, 0.f);
            v1.y = fmaxf(cacc[mi][ni][3] + b1, 0.f);
            *(float2*)&g_h[(size_t)row0 * HID + col]       = v0;
            *(float2*)&g_h[(size_t)(row0 + 8) * HID + col] = v1;
        }
    }
}

// ---------------- s_logits, softmax s, per-graph ss/den ----------------
__global__ void s_kernel(const float* __restrict__ Wp,
                         const float* __restrict__ bp,
                         float* __restrict__ dout) {
    __shared__ float red[8][4];
    int wip = threadIdx.x >> 5;
    int lane = threadIdx.x & 31;
    int node = blockIdx.x * 8 + wip;
    const float* hrow = g_h + (size_t)node * HID;
    float d0 = 0.f, d1 = 0.f;
    for (int k = lane; k < HID; k += 32) {
        float hv = hrow[k];
        d0 += hv * Wp[k * 2];
        d1 += hv * Wp[k * 2 + 1];
    }
    d0 = wred(d0); d1 = wred(d1);
    if (lane == 0) {
        d0 += bp[0]; d1 += bp[1];
        dout[OUT_SLOG + node * 2]     = d0;
        dout[OUT_SLOG + node * 2 + 1] = d1;
        float m = fmaxf(d0, d1);
        float e0 = expf(d0 - m), e1 = expf(d1 - m);
        float inv = 1.f / (e0 + e1);
        float s0 = e0 * inv, s1 = e1 * inv;
        g_s[node * 2] = s0; g_s[node * 2 + 1] = s1;
        float dn = g_d[node];
        red[wip][0] = s0 * s0;
        red[wip][1] = s0 * s1;
        red[wip][2] = s1 * s1;
        red[wip][3] = dn * (s0 * s0 + s1 * s1);
    }
    __syncthreads();
    if (threadIdx.x < 4) {
        int b = node >> 12;
        float t = 0.f;
#pragma unroll
        for (int w = 0; w < 8; w++) t += red[w][threadIdx.x];
        atomicAdd(&g_accum[b * 4 + threadIdx.x], t);
    }
}

// ---------------- out[b,c,f] = sum_n s[n,c]*h[n,f] ----------------------
__global__ void pool_kernel() {
    int b = blockIdx.x;
    int f = blockIdx.y * 128 + threadIdx.x;
    int ns = blockIdx.z;
    int nb = b * NLOC + ns * 512;
    float a0 = 0.f, a1 = 0.f;
    for (int n = 0; n < 512; n++) {
        int node = nb + n;
        float hv = g_h[(size_t)node * HID + f];
        a0 += g_s[node * 2] * hv;
        a1 += g_s[node * 2 + 1] * hv;
    }
    atomicAdd(&g_out[(b * 2 + 0) * HID + f], a0);
    atomicAdd(&g_out[(b * 2 + 1) * HID + f], a1);
}

// ---------------- out_adj[b,c,k] = sum_e s[src,c]*w*s[dst,k] ------------
__global__ void oa_kernel(const int* __restrict__ ei,
                          const float* __restrict__ ew) {
    __shared__ float red[8][4];
    int e = blockIdx.x * 256 + threadIdx.x;
    int src = ei[e];
    int dst = ei[NEDGE + e];
    float w = ew[e];
    float ss0 = g_s[src * 2], ss1 = g_s[src * 2 + 1];
    float sd0 = g_s[dst * 2], sd1 = g_s[dst * 2 + 1];
    float v00 = ss0 * w * sd0, v01 = ss0 * w * sd1;
    float v10 = ss1 * w * sd0, v11 = ss1 * w * sd1;
    v00 = wred(v00); v01 = wred(v01); v10 = wred(v10); v11 = wred(v11);
    int wip = threadIdx.x >> 5;
    if ((threadIdx.x & 31) == 0) {
        red[wip][0] = v00; red[wip][1] = v01; red[wip][2] = v10; red[wip][3] = v11;
    }
    __syncthreads();
    if (threadIdx.x < 4) {
        int b = src >> 12;
        float t = 0.f;
#pragma unroll
        for (int w2 = 0; w2 < 8; w2++) t += red[w2][threadIdx.x];
        atomicAdd(&g_oaraw[b * 4 + threadIdx.x], t);
    }
}

// ---------------- per-graph losses + out_adj normalization --------------
__global__ void finalize_kernel(float* __restrict__ dout) {
    int b = threadIdx.x;
    float mc = 0.f, ol = 0.f;
    if (b < NGR) {
        float a00 = g_oaraw[b * 4 + 0], a01 = g_oaraw[b * 4 + 1];
        float a10 = g_oaraw[b * 4 + 2], a11 = g_oaraw[b * 4 + 3];
        float num = a00 + a11;
        float den = g_accum[b * 4 + 3];
        mc = -(num / den);
        float ss00 = g_accum[b * 4 + 0], ss01 = g_accum[b * 4 + 1], ss11 = g_accum[b * 4 + 2];
        float nrm = sqrtf(ss00 * ss00 + 2.f * ss01 * ss01 + ss11 * ss11);
        const float q = 0.70710678118654752f;
        float n00 = ss00 / nrm - q, n01 = ss01 / nrm, n11 = ss11 / nrm - q;
        ol = sqrtf(n00 * n00 + 2.f * n01 * n01 + n11 * n11);
        float d2_0 = sqrtf(a01) + 1e-15f;
        float d2_1 = sqrtf(a10) + 1e-15f;
        float oa01 = a01 / (d2_0 * d2_1);
        float oa10 = a10 / (d2_1 * d2_0);
        g_oan[b * 4 + 0] = 0.f; g_oan[b * 4 + 1] = oa01;
        g_oan[b * 4 + 2] = oa10; g_oan[b * 4 + 3] = 0.f;
        dout[OUT_OA + b * 4 + 0] = 0.f;
        dout[OUT_OA + b * 4 + 1] = oa01;
        dout[OUT_OA + b * 4 + 2] = oa10;
        dout[OUT_OA + b * 4 + 3] = 0.f;
    }
    mc = wred(mc); ol = wred(ol);
    if (threadIdx.x == 0) {
        dout[OUT_MC] = mc / (float)NGR;
        dout[OUT_OL] = ol / (float)NGR;
    }
}

// ---------------- xm = mean_c(agg3@W_rel3 + b + out@W_root3) ------------
__global__ void xm_kernel(const float* __restrict__ Wrel3,
                          const float* __restrict__ brel3,
                          const float* __restrict__ Wroot3) {
    int b = blockIdx.x >> 1;
    int f = ((blockIdx.x & 1) << 8) + threadIdx.x;
    float oa01 = g_oan[b * 4 + 1], oa10 = g_oan[b * 4 + 2];
    const float* o0 = &g_out[(b * 2 + 0) * HID];
    const float* o1 = &g_out[(b * 2 + 1) * HID];
    float acc = 0.f;
    for (int k = 0; k < HID; k++) {
        float u = oa10 * o1[k] + oa01 * o0[k];
        float v = o0[k] + o1[k];
        acc += u * Wrel3[k * HID + f] + v * Wroot3[k * HID + f];
    }
    g_xm[b * HID + f] = 0.5f * acc + brel3[f];
}

// ---------------- h2 = relu(xm @ W_lin1 + b) ----------------------------
__global__ void h2_kernel(const float* __restrict__ Wlin1,
                          const float* __restrict__ blin1) {
    int b = blockIdx.x >> 1;
    int f = ((blockIdx.x & 1) << 8) + threadIdx.x;
    float acc = 0.f;
    for (int k = 0; k < HID; k++)
        acc += g_xm[b * HID + k] * Wlin1[k * HID + f];
    g_h2[b * HID + f] = fmaxf(acc + blin1[f], 0.f);
}

// ---------------- logits + log_softmax ----------------------------------
__global__ void logits_kernel(const float* __restrict__ Wlin2,
                              const float* __restrict__ blin2,
                              float* __restrict__ dout) {
    __shared__ float lg[10];
    int b = blockIdx.x;
    int o = threadIdx.x >> 5;
    int lane = threadIdx.x & 31;
    float acc = 0.f;
    for (int k = lane; k < HID; k += 32)
        acc += g_h2[b * HID + k] * Wlin2[k * 10 + o];
    acc = wred(acc);
    if (lane == 0) lg[o] = acc + blin2[o];
    __syncthreads();
    if (threadIdx.x == 0) {
        float m = lg[0];
#pragma unroll
        for (int i = 1; i < 10; i++) m = fmaxf(m, lg[i]);
        float s = 0.f;
#pragma unroll
        for (int i = 0; i < 10; i++) s += expf(lg[i] - m);
        float lse = logf(s) + m;
#pragma unroll
        for (int i = 0; i < 10; i++) dout[b * 10 + i] = lg[i] - lse;
    }
}

extern "C" void kernel_launch(void* const* d_in, const int* in_sizes, int n_in,
                              void* d_out, int out_size) {
    const float* x       = (const float*)d_in[0];
    const int*   ei      = (const int*)d_in[1];   // int32 (JAX x64 disabled)
    const float* ew      = (const float*)d_in[3];
    const float* W_rel1  = (const float*)d_in[4];
    const float* b_rel1  = (const float*)d_in[5];
    const float* W_root1 = (const float*)d_in[6];
    const float* W_pool  = (const float*)d_in[7];
    const float* b_pool  = (const float*)d_in[8];
    const float* W_rel3  = (const float*)d_in[9];
    const float* b_rel3  = (const float*)d_in[10];
    const float* W_root3 = (const float*)d_in[11];
    const float* W_lin1  = (const float*)d_in[12];
    const float* b_lin1  = (const float*)d_in[13];
    const float* W_lin2  = (const float*)d_in[14];
    const float* b_lin2  = (const float*)d_in[15];
    float* out = (float*)d_out;

    zero_kernel<<<129, 256>>>();
    count_kernel<<<NEDGE / 256, 256>>>(ei, ew);
    scan_kernel<<<1, 1024>>>();
    scatter_kernel<<<NEDGE / 256, 256>>>(ei, ew);
    agg_kernel<<<NNODE / 8, 256>>>(x);
    gemm_h_tc<<<dim3(NNODE / 128, HID / 128), 256>>>(x, W_rel1, W_root1, b_rel1);
    s_kernel<<<NNODE / 8, 256>>>(W_pool, b_pool, out);
    pool_kernel<<<dim3(NGR, 4, 8), 128>>>();
    oa_kernel<<<NEDGE / 256, 256>>>(ei, ew);
    finalize_kernel<<<1, 32>>>(out);
    xm_kernel<<<16, 256>>>(W_rel3, b_rel3, W_root3);
    h2_kernel<<<16, 256>>>(W_lin1, b_lin1);
    logits_kernel<<<8, 320>>>(W_lin2, b_lin2, out);
}

// round 4
// speedup vs baseline: 1.1717x; 1.0105x over previous
#include <cuda_runtime.h>
#include <math.h>
#include <stdint.h>

#define NEDGE 524288
#define NNODE 32768
#define NGR   8
#define NLOC  4096
#define FIN   128
#define HID   512

#define OUT_MC    80
#define OUT_OL    81
#define OUT_SLOG  82
#define OUT_OA    65618

// ---- scratch ----
__device__ float g_agg[NNODE * FIN];
__device__ float g_Aext[NNODE * 512];      // [A_hi | A_lo], 64MB
__device__ float g_Bext[768 * 512];        // [B_hi; B_hi; B_lo]
__device__ float g_h[NNODE * HID];
__device__ float g_s[NNODE * 2];
__device__ int   g_cnt[NNODE + 1];
__device__ int   g_offs[NNODE + 1];
__device__ int   g_cursor[NNODE];
__device__ int   g_ssrc[NEDGE];
__device__ float g_sw[NEDGE];
__device__ float g_d[NNODE];
__device__ float g_accum[NGR * 4];
__device__ float g_oaraw[NGR * 4];
__device__ float g_oan[NGR * 4];
__device__ float g_out[NGR * 2 * HID];
__device__ float g_xm[NGR * HID];
__device__ float g_h2[NGR * HID];

__device__ __forceinline__ float wred(float v) {
#pragma unroll
    for (int o = 16; o; o >>= 1) v += __shfl_down_sync(0xffffffffu, v, o);
    return v;
}

__device__ __forceinline__ void cvt_hilo(float v, float& hi, float& lo) {
    uint32_t u;
    asm("cvt.rna.tf32.f32 %0, %1;" : "=r"(u) : "f"(v));
    hi = __uint_as_float(u);
    float rem = v - hi;
    uint32_t u2;
    asm("cvt.rna.tf32.f32 %0, %1;" : "=r"(u2) : "f"(rem));
    lo = __uint_as_float(u2);
}

#define MMA_TF32(d, a0, a1, a2, a3, b0, b1)                                   \
    asm volatile(                                                             \
        "mma.sync.aligned.m16n8k8.row.col.f32.tf32.tf32.f32 "                 \
        "{%0,%1,%2,%3},{%4,%5,%6,%7},{%8,%9},{%0,%1,%2,%3};"                  \
        : "+f"(d[0]), "+f"(d[1]), "+f"(d[2]), "+f"(d[3])                      \
        : "r"(__float_as_uint(a0)), "r"(__float_as_uint(a1)),                 \
          "r"(__float_as_uint(a2)), "r"(__float_as_uint(a3)),                 \
          "r"(__float_as_uint(b0)), "r"(__float_as_uint(b1)))

__device__ __forceinline__ void cp16(void* smem_dst, const void* gsrc) {
    uint32_t sp = (uint32_t)__cvta_generic_to_shared(smem_dst);
    asm volatile("cp.async.cg.shared.global [%0], [%1], 16;\n"
                 :: "r"(sp), "l"(gsrc) : "memory");
}
__device__ __forceinline__ void cp_commit() {
    asm volatile("cp.async.commit_group;\n" ::: "memory");
}

// ---------------- zero scratch ----------------
__global__ void zero_kernel() {
    int i = blockIdx.x * 256 + threadIdx.x;
    if (i < NNODE + 1) g_cnt[i] = 0;
    if (i < NNODE)     g_d[i] = 0.f;
    if (i < NGR * 2 * HID) g_out[i] = 0.f;
    if (i < NGR * 4) { g_accum[i] = 0.f; g_oaraw[i] = 0.f; }
}

// ---------------- count by dst + degree by src ----------------
__global__ void count_kernel(const int* __restrict__ ei,
                             const float* __restrict__ ew) {
    int e = blockIdx.x * 256 + threadIdx.x;
    if (e >= NEDGE) return;
    int src = ei[e];
    int dst = ei[NEDGE + e];
    atomicAdd(&g_cnt[dst], 1);
    atomicAdd(&g_d[src], ew[e]);
}

// ---------------- exclusive scan (1 block, 1024 thr) ----------------
__global__ void scan_kernel() {
    __shared__ int sm[1024];
    int tid = threadIdx.x;
    int base = tid * 32;
    int sum = 0;
#pragma unroll
    for (int i = 0; i < 32; i++) sum += g_cnt[base + i];
    sm[tid] = sum;
    __syncthreads();
    for (int o = 1; o < 1024; o <<= 1) {
        int v = (tid >= o) ? sm[tid - o] : 0;
        __syncthreads();
        sm[tid] += v;
        __syncthreads();
    }
    int run = sm[tid] - sum;
#pragma unroll
    for (int i = 0; i < 32; i++) {
        int c = g_cnt[base + i];
        g_offs[base + i] = run;
        g_cursor[base + i] = run;
        run += c;
    }
    if (tid == 1023) g_offs[NNODE] = run;
}

// ---------------- scatter edges sorted by dst ----------------
__global__ void scatter_kernel(const int* __restrict__ ei,
                               const float* __restrict__ ew) {
    int e = blockIdx.x * 256 + threadIdx.x;
    if (e >= NEDGE) return;
    int src = ei[e];
    int dst = ei[NEDGE + e];
    int pos = atomicAdd(&g_cursor[dst], 1);
    g_ssrc[pos] = src;
    g_sw[pos]   = ew[e];
}

// ---------------- agg[dst] = sum w * x[src]  (warp per dst) ------------
__global__ void agg_kernel(const float* __restrict__ x) {
    int gwarp = (blockIdx.x * 256 + threadIdx.x) >> 5;
    int lane  = threadIdx.x & 31;
    int s0 = g_offs[gwarp], s1 = g_offs[gwarp + 1];
    const float4* x4 = (const float4*)x;
    float4 acc = make_float4(0.f, 0.f, 0.f, 0.f);
    for (int e = s0; e < s1; e++) {
        int sn = g_ssrc[e];
        float w = g_sw[e];
        float4 v = x4[sn * 32 + lane];
        acc.x += w * v.x; acc.y += w * v.y; acc.z += w * v.z; acc.w += w * v.w;
    }
    ((float4*)g_agg)[gwarp * 32 + lane] = acc;
}

// ---------------- build A_ext = [hi(agg|x) | lo(agg|x)] ------------------
__global__ void cvtA_kernel(const float* __restrict__ x) {
    int idx = blockIdx.x * 256 + threadIdx.x;   // float4 id, 32768*64 total
    int row = idx >> 6;
    int c4  = (idx & 63) * 4;                   // 0..252
    const float* src = (c4 < 128) ? (g_agg + (size_t)row * 128 + c4)
                                  : (x + (size_t)row * 128 + (c4 - 128));
    float4 v = *(const float4*)src;
    float4 vh, vl;
    cvt_hilo(v.x, vh.x, vl.x);
    cvt_hilo(v.y, vh.y, vl.y);
    cvt_hilo(v.z, vh.z, vl.z);
    cvt_hilo(v.w, vh.w, vl.w);
    *(float4*)&g_Aext[(size_t)row * 512 + c4]       = vh;
    *(float4*)&g_Aext[(size_t)row * 512 + 256 + c4] = vl;
}

// ---------------- build B_ext = [Whi; Whi; Wlo]  (W = [W1;W2]) ----------
__global__ void cvtB_kernel(const float* __restrict__ W1,
                            const float* __restrict__ W2) {
    int idx = blockIdx.x * 256 + threadIdx.x;   // float4 id, 256*128 total
    int row = idx >> 7;                          // 0..255
    int c4  = (idx & 127) * 4;
    const float* src = (row < 128) ? &W1[(size_t)row * 512 + c4]
                                   : &W2[(size_t)(row - 128) * 512 + c4];
    float4 v = *(const float4*)src;
    float4 vh, vl;
    cvt_hilo(v.x, vh.x, vl.x);
    cvt_hilo(v.y, vh.y, vl.y);
    cvt_hilo(v.z, vh.z, vl.z);
    cvt_hilo(v.w, vh.w, vl.w);
    *(float4*)&g_Bext[(size_t)row * 512 + c4]         = vh;
    *(float4*)&g_Bext[(size_t)(256 + row) * 512 + c4] = vh;
    *(float4*)&g_Bext[(size_t)(512 + row) * 512 + c4] = vl;
}

// ---------------- h = relu(A_ext @ B_ext + b)  pipelined tf32 GEMM -------
// 128x128 tile, BK=32, 24 stages, cp.async double buffer.
// A smem pad 36 (conflict-free: bank = 4*row+col), B pad 136 (8*krow+q).
#define AS_STRIDE 36
#define BS_STRIDE 136
#define AS_BUF (128 * AS_STRIDE)
#define BS_BUF (32 * BS_STRIDE)
#define GEMM_SMEM ((2 * AS_BUF + 2 * BS_BUF) * 4)

__global__ __launch_bounds__(256) void gemm_h_tc(const float* __restrict__ bias) {
    extern __shared__ float smem[];
    float* Asm[2] = { smem, smem + AS_BUF };
    float* Bsm[2] = { smem + 2 * AS_BUF, smem + 2 * AS_BUF + BS_BUF };

    int tid  = threadIdx.x;
    int lane = tid & 31;
    int wid  = tid >> 5;
    int warp_m = wid & 1;
    int warp_n = wid >> 1;
    int bm = blockIdx.y * 128;
    int bn = blockIdx.x * 128;

    float cacc[4][4][4];
#pragma unroll
    for (int i = 0; i < 4; i++)
#pragma unroll
        for (int j = 0; j < 4; j++)
#pragma unroll
            for (int r = 0; r < 4; r++) cacc[i][j][r] = 0.f;

    // stage loader: stage kt -> A cols, B rows
    auto load_stage = [&](int kt, int buf) {
        int seg = kt >> 3;                       // 0,1,2
        int kA  = ((kt & 7) << 5) + (seg == 1 ? 256 : 0);  // hi, lo, hi
        int kB  = kt << 5;
#pragma unroll
        for (int t = 0; t < 4; t++) {
            int id  = tid + t * 256;             // 0..1023
            int r   = id >> 3;                   // 0..127
            int c4  = (id & 7) * 4;              // 0..28
            cp16(&Asm[buf][r * AS_STRIDE + c4],
                 &g_Aext[(size_t)(bm + r) * 512 + kA + c4]);
        }
#pragma unroll
        for (int t = 0; t < 4; t++) {
            int id  = tid + t * 256;
            int r   = id >> 5;                   // 0..31
            int c4  = (id & 31) * 4;             // 0..124
            cp16(&Bsm[buf][r * BS_STRIDE + c4],
                 &g_Bext[(size_t)(kB + r) * 512 + bn + c4]);
        }
        cp_commit();
    };

    load_stage(0, 0);

    for (int kt = 0; kt < 24; kt++) {
        if (kt < 23) {
            load_stage(kt + 1, (kt + 1) & 1);
            asm volatile("cp.async.wait_group 1;\n" ::: "memory");
        } else {
            asm volatile("cp.async.wait_group 0;\n" ::: "memory");
        }
        __syncthreads();

        const float* As = Asm[kt & 1];
        const float* Bs = Bsm[kt & 1];
#pragma unroll
        for (int k8 = 0; k8 < 4; k8++) {
            int kb = k8 * 8;
            float a[4][4];
#pragma unroll
            for (int mi = 0; mi < 4; mi++) {
                int row = warp_m * 64 + mi * 16 + (lane >> 2);
                int col = kb + (lane & 3);
                a[mi][0] = As[row * AS_STRIDE + col];
                a[mi][1] = As[(row + 8) * AS_STRIDE + col];
                a[mi][2] = As[row * AS_STRIDE + col + 4];
                a[mi][3] = As[(row + 8) * AS_STRIDE + col + 4];
            }
#pragma unroll
            for (int ni = 0; ni < 4; ni++) {
                int ncol = warp_n * 32 + ni * 8 + (lane >> 2);
                int krow = kb + (lane & 3);
                float b0 = Bs[krow * BS_STRIDE + ncol];
                float b1 = Bs[(krow + 4) * BS_STRIDE + ncol];
#pragma unroll
                for (int mi = 0; mi < 4; mi++)
                    MMA_TF32(cacc[mi][ni], a[mi][0], a[mi][1], a[mi][2], a[mi][3], b0, b1);
            }
        }
        __syncthreads();
    }

    // epilogue: bias + relu
#pragma unroll
    for (int mi = 0; mi < 4; mi++) {
        int row0 = bm + warp_m * 64 + mi * 16 + (lane >> 2);
#pragma unroll
        for (int ni = 0; ni < 4; ni++) {
            int col = bn + warp_n * 32 + ni * 8 + 2 * (lane & 3);
            float b0 = bias[col], b1 = bias[col + 1];
            float2 v0, v1;
            v0.x = fmaxf(cacc[mi][ni][0] + b0, 0.f);
            v0.y = fmaxf(cacc[mi][ni][1] + b1, 0.f);
            v1.x = fmaxf(cacc[mi][ni][2] + b0, 0.f);
            v1.y = fmaxf(cacc[mi][ni][3] + b1, 0.f);
            *(float2*)&g_h[(size_t)row0 * HID + col]       = v0;
            *(float2*)&g_h[(size_t)(row0 + 8) * HID + col] = v1;
        }
    }
}

// ---------------- s_logits, softmax s, per-graph ss/den ----------------
__global__ void s_kernel(const float* __restrict__ Wp,
                         const float* __restrict__ bp,
                         float* __restrict__ dout) {
    __shared__ float red[8][4];
    int wip = threadIdx.x >> 5;
    int lane = threadIdx.x & 31;
    int node = blockIdx.x * 8 + wip;
    const float* hrow = g_h + (size_t)node * HID;
    float d0 = 0.f, d1 = 0.f;
    for (int k = lane; k < HID; k += 32) {
        float hv = hrow[k];
        d0 += hv * Wp[k * 2];
        d1 += hv * Wp[k * 2 + 1];
    }
    d0 = wred(d0); d1 = wred(d1);
    if (lane == 0) {
        d0 += bp[0]; d1 += bp[1];
        dout[OUT_SLOG + node * 2]     = d0;
        dout[OUT_SLOG + node * 2 + 1] = d1;
        float m = fmaxf(d0, d1);
        float e0 = expf(d0 - m), e1 = expf(d1 - m);
        float inv = 1.f / (e0 + e1);
        float s0 = e0 * inv, s1 = e1 * inv;
        g_s[node * 2] = s0; g_s[node * 2 + 1] = s1;
        float dn = g_d[node];
        red[wip][0] = s0 * s0;
        red[wip][1] = s0 * s1;
        red[wip][2] = s1 * s1;
        red[wip][3] = dn * (s0 * s0 + s1 * s1);
    }
    __syncthreads();
    if (threadIdx.x < 4) {
        int b = node >> 12;
        float t = 0.f;
#pragma unroll
        for (int w = 0; w < 8; w++) t += red[w][threadIdx.x];
        atomicAdd(&g_accum[b * 4 + threadIdx.x], t);
    }
}

// ---------------- out[b,c,f] = sum_n s[n,c]*h[n,f] ----------------------
__global__ void pool_kernel() {
    int b = blockIdx.x;
    int f = blockIdx.y * 128 + threadIdx.x;
    int ns = blockIdx.z;
    int nb = b * NLOC + ns * 512;
    float a0 = 0.f, a1 = 0.f;
    for (int n = 0; n < 512; n++) {
        int node = nb + n;
        float hv = g_h[(size_t)node * HID + f];
        a0 += g_s[node * 2] * hv;
        a1 += g_s[node * 2 + 1] * hv;
    }
    atomicAdd(&g_out[(b * 2 + 0) * HID + f], a0);
    atomicAdd(&g_out[(b * 2 + 1) * HID + f], a1);
}

// ---------------- out_adj[b,c,k] = sum_e s[src,c]*w*s[dst,k] ------------
__global__ void oa_kernel(const int* __restrict__ ei,
                          const float* __restrict__ ew) {
    __shared__ float red[8][4];
    int e = blockIdx.x * 256 + threadIdx.x;
    int src = ei[e];
    int dst = ei[NEDGE + e];
    float w = ew[e];
    float ss0 = g_s[src * 2], ss1 = g_s[src * 2 + 1];
    float sd0 = g_s[dst * 2], sd1 = g_s[dst * 2 + 1];
    float v00 = ss0 * w * sd0, v01 = ss0 * w * sd1;
    float v10 = ss1 * w * sd0, v11 = ss1 * w * sd1;
    v00 = wred(v00); v01 = wred(v01); v10 = wred(v10); v11 = wred(v11);
    int wip = threadIdx.x >> 5;
    if ((threadIdx.x & 31) == 0) {
        red[wip][0] = v00; red[wip][1] = v01; red[wip][2] = v10; red[wip][3] = v11;
    }
    __syncthreads();
    if (threadIdx.x < 4) {
        int b = src >> 12;
        float t = 0.f;
#pragma unroll
        for (int w2 = 0; w2 < 8; w2++) t += red[w2][threadIdx.x];
        atomicAdd(&g_oaraw[b * 4 + threadIdx.x], t);
    }
}

// ---------------- per-graph losses + out_adj normalization --------------
__global__ void finalize_kernel(float* __restrict__ dout) {
    int b = threadIdx.x;
    float mc = 0.f, ol = 0.f;
    if (b < NGR) {
        float a00 = g_oaraw[b * 4 + 0], a01 = g_oaraw[b * 4 + 1];
        float a10 = g_oaraw[b * 4 + 2], a11 = g_oaraw[b * 4 + 3];
        float num = a00 + a11;
        float den = g_accum[b * 4 + 3];
        mc = -(num / den);
        float ss00 = g_accum[b * 4 + 0], ss01 = g_accum[b * 4 + 1], ss11 = g_accum[b * 4 + 2];
        float nrm = sqrtf(ss00 * ss00 + 2.f * ss01 * ss01 + ss11 * ss11);
        const float q = 0.70710678118654752f;
        float n00 = ss00 / nrm - q, n01 = ss01 / nrm, n11 = ss11 / nrm - q;
        ol = sqrtf(n00 * n00 + 2.f * n01 * n01 + n11 * n11);
        float d2_0 = sqrtf(a01) + 1e-15f;
        float d2_1 = sqrtf(a10) + 1e-15f;
        float oa01 = a01 / (d2_0 * d2_1);
        float oa10 = a10 / (d2_1 * d2_0);
        g_oan[b * 4 + 0] = 0.f; g_oan[b * 4 + 1] = oa01;
        g_oan[b * 4 + 2] = oa10; g_oan[b * 4 + 3] = 0.f;
        dout[OUT_OA + b * 4 + 0] = 0.f;
        dout[OUT_OA + b * 4 + 1] = oa01;
        dout[OUT_OA + b * 4 + 2] = oa10;
        dout[OUT_OA + b * 4 + 3] = 0.f;
    }
    mc = wred(mc); ol = wred(ol);
    if (threadIdx.x == 0) {
        dout[OUT_MC] = mc / (float)NGR;
        dout[OUT_OL] = ol / (float)NGR;
    }
}

// ---------------- xm = mean_c(agg3@W_rel3 + b + out@W_root3) ------------
__global__ void xm_kernel(const float* __restrict__ Wrel3,
                          const float* __restrict__ brel3,
                          const float* __restrict__ Wroot3) {
    int b = blockIdx.x >> 1;
    int f = ((blockIdx.x & 1) << 8) + threadIdx.x;
    float oa01 = g_oan[b * 4 + 1], oa10 = g_oan[b * 4 + 2];
    const float* o0 = &g_out[(b * 2 + 0) * HID];
    const float* o1 = &g_out[(b * 2 + 1) * HID];
    float acc = 0.f;
    for (int k = 0; k < HID; k++) {
        float u = oa10 * o1[k] + oa01 * o0[k];
        float v = o0[k] + o1[k];
        acc += u * Wrel3[k * HID + f] + v * Wroot3[k * HID + f];
    }
    g_xm[b * HID + f] = 0.5f * acc + brel3[f];
}

// ---------------- h2 = relu(xm @ W_lin1 + b) ----------------------------
__global__ void h2_kernel(const float* __restrict__ Wlin1,
                          const float* __restrict__ blin1) {
    int b = blockIdx.x >> 1;
    int f = ((blockIdx.x & 1) << 8) + threadIdx.x;
    float acc = 0.f;
    for (int k = 0; k < HID; k++)
        acc += g_xm[b * HID + k] * Wlin1[k * HID + f];
    g_h2[b * HID + f] = fmaxf(acc + blin1[f], 0.f);
}

// ---------------- logits + log_softmax ----------------------------------
__global__ void logits_kernel(const float* __restrict__ Wlin2,
                              const float* __restrict__ blin2,
                              float* __restrict__ dout) {
    __shared__ float lg[10];
    int b = blockIdx.x;
    int o = threadIdx.x >> 5;
    int lane = threadIdx.x & 31;
    float acc = 0.f;
    for (int k = lane; k < HID; k += 32)
        acc += g_h2[b * HID + k] * Wlin2[k * 10 + o];
    acc = wred(acc);
    if (lane == 0) lg[o] = acc + blin2[o];
    __syncthreads();
    if (threadIdx.x == 0) {
        float m = lg[0];
#pragma unroll
        for (int i = 1; i < 10; i++) m = fmaxf(m, lg[i]);
        float s = 0.f;
#pragma unroll
        for (int i = 0; i < 10; i++) s += expf(lg[i] - m);
        float lse = logf(s) + m;
#pragma unroll
        for (int i = 0; i < 10; i++) dout[b * 10 + i] = lg[i] - lse;
    }
}

extern "C" void kernel_launch(void* const* d_in, const int* in_sizes, int n_in,
                              void* d_out, int out_size) {
    const float* x       = (const float*)d_in[0];
    const int*   ei      = (const int*)d_in[1];   // int32 (JAX x64 disabled)
    const float* ew      = (const float*)d_in[3];
    const float* W_rel1  = (const float*)d_in[4];
    const float* b_rel1  = (const float*)d_in[5];
    const float* W_root1 = (const float*)d_in[6];
    const float* W_pool  = (const float*)d_in[7];
    const float* b_pool  = (const float*)d_in[8];
    const float* W_rel3  = (const float*)d_in[9];
    const float* b_rel3  = (const float*)d_in[10];
    const float* W_root3 = (const float*)d_in[11];
    const float* W_lin1  = (const float*)d_in[12];
    const float* b_lin1  = (const float*)d_in[13];
    const float* W_lin2  = (const float*)d_in[14];
    const float* b_lin2  = (const float*)d_in[15];
    float* out = (float*)d_out;

    static int smem_set = 0;
    if (!smem_set) {
        cudaFuncSetAttribute(gemm_h_tc, cudaFuncAttributeMaxDynamicSharedMemorySize,
                             GEMM_SMEM);
        smem_set = 1;
    }

    zero_kernel<<<129, 256>>>();
    count_kernel<<<NEDGE / 256, 256>>>(ei, ew);
    scan_kernel<<<1, 1024>>>();
    scatter_kernel<<<NEDGE / 256, 256>>>(ei, ew);
    agg_kernel<<<NNODE / 8, 256>>>(x);
    cvtA_kernel<<<NNODE * 64 / 256, 256>>>(x);
    cvtB_kernel<<<128, 256>>>(W_rel1, W_root1);
    gemm_h_tc<<<dim3(HID / 128, NNODE / 128), 256, GEMM_SMEM>>>(b_rel1);
    s_kernel<<<NNODE / 8, 256>>>(W_pool, b_pool, out);
    pool_kernel<<<dim3(NGR, 4, 8), 128>>>();
    oa_kernel<<<NEDGE / 256, 256>>>(ei, ew);
    finalize_kernel<<<1, 32>>>(out);
    xm_kernel<<<16, 256>>>(W_rel3, b_rel3, W_root3);
    h2_kernel<<<16, 256>>>(W_lin1, b_lin1);
    logits_kernel<<<8, 320>>>(W_lin2, b_lin2, out);
}

// round 6
// speedup vs baseline: 1.4229x; 1.2143x over previous
#include <cuda_runtime.h>
#include <cuda_bf16.h>
#include <math.h>
#include <stdint.h>

#define NEDGE 524288
#define NNODE 32768
#define NGR   8
#define NLOC  4096
#define FIN   128
#define HID   512

#define OUT_MC    80
#define OUT_OL    81
#define OUT_SLOG  82
#define OUT_OA    65618

// ---- scratch ----
__device__ float          g_agg[NNODE * FIN];
__device__ __nv_bfloat16  g_Ab[NNODE * 512];     // [hi(agg|x) | lo(agg|x)]
__device__ __nv_bfloat16  g_Bt[512 * 768];       // Bt[n][k]: k = [hi|hi|lo] of W=[W1;W2]
__device__ float g_h[NNODE * HID];
__device__ float g_s[NNODE * 2];
__device__ int   g_cnt[NNODE + 1];
__device__ int   g_offs[NNODE + 1];
__device__ int   g_cursor[NNODE];
__device__ int   g_ssrc[NEDGE];
__device__ float g_sw[NEDGE];
__device__ float g_d[NNODE];
__device__ float g_accum[NGR * 4];
__device__ float g_oaraw[NGR * 4];
__device__ float g_oan[NGR * 4];
__device__ float g_out[NGR * 2 * HID];
__device__ float g_xm[NGR * HID];
__device__ float g_h2[NGR * HID];

__device__ __forceinline__ float wred(float v) {
#pragma unroll
    for (int o = 16; o; o >>= 1) v += __shfl_down_sync(0xffffffffu, v, o);
    return v;
}

#define SMEM_SWZ(o) ((o) ^ (((o) >> 3) & 0x70))

__device__ __forceinline__ uint32_t smem_u32(const void* p) {
    return (uint32_t)__cvta_generic_to_shared(p);
}
__device__ __forceinline__ void cp16s(uint32_t saddr, const void* g) {
    asm volatile("cp.async.cg.shared.global [%0], [%1], 16;"
                 :: "r"(saddr), "l"(g) : "memory");
}
__device__ __forceinline__ void ldsm4(uint32_t* r, uint32_t a) {
    asm volatile("ldmatrix.sync.aligned.m8n8.x4.shared.b16 {%0,%1,%2,%3}, [%4];"
                 : "=r"(r[0]), "=r"(r[1]), "=r"(r[2]), "=r"(r[3]) : "r"(a));
}
__device__ __forceinline__ void ldsm2(uint32_t* r, uint32_t a) {
    asm volatile("ldmatrix.sync.aligned.m8n8.x2.shared.b16 {%0,%1}, [%2];"
                 : "=r"(r[0]), "=r"(r[1]) : "r"(a));
}
#define MMA_BF16(d, a, b)                                                     \
    asm volatile(                                                             \
        "mma.sync.aligned.m16n8k16.row.col.f32.bf16.bf16.f32 "                \
        "{%0,%1,%2,%3},{%4,%5,%6,%7},{%8,%9},{%0,%1,%2,%3};"                  \
        : "+f"((d)[0]), "+f"((d)[1]), "+f"((d)[2]), "+f"((d)[3])              \
        : "r"((a)[0]), "r"((a)[1]), "r"((a)[2]), "r"((a)[3]),                 \
          "r"((b)[0]), "r"((b)[1]))

// ---------------- zero scratch ----------------
__global__ void zero_kernel() {
    int i = blockIdx.x * 256 + threadIdx.x;
    if (i < NNODE + 1) g_cnt[i] = 0;
    if (i < NNODE)     g_d[i] = 0.f;
    if (i < NGR * 2 * HID) g_out[i] = 0.f;
    if (i < NGR * 4) { g_accum[i] = 0.f; g_oaraw[i] = 0.f; }
}

// ---------------- count by dst + degree by src ----------------
__global__ void count_kernel(const int* __restrict__ ei,
                             const float* __restrict__ ew) {
    int e = blockIdx.x * 256 + threadIdx.x;
    if (e >= NEDGE) return;
    int src = ei[e];
    int dst = ei[NEDGE + e];
    atomicAdd(&g_cnt[dst], 1);
    atomicAdd(&g_d[src], ew[e]);
}

// ---------------- exclusive scan (1 block, 1024 thr) ----------------
__global__ void scan_kernel() {
    __shared__ int sm[1024];
    int tid = threadIdx.x;
    int base = tid * 32;
    int sum = 0;
#pragma unroll
    for (int i = 0; i < 32; i++) sum += g_cnt[base + i];
    sm[tid] = sum;
    __syncthreads();
    for (int o = 1; o < 1024; o <<= 1) {
        int v = (tid >= o) ? sm[tid - o] : 0;
        __syncthreads();
        sm[tid] += v;
        __syncthreads();
    }
    int run = sm[tid] - sum;
#pragma unroll
    for (int i = 0; i < 32; i++) {
        int c = g_cnt[base + i];
        g_offs[base + i] = run;
        g_cursor[base + i] = run;
        run += c;
    }
    if (tid == 1023) g_offs[NNODE] = run;
}

// ---------------- scatter edges sorted by dst ----------------
__global__ void scatter_kernel(const int* __restrict__ ei,
                               const float* __restrict__ ew) {
    int e = blockIdx.x * 256 + threadIdx.x;
    if (e >= NEDGE) return;
    int src = ei[e];
    int dst = ei[NEDGE + e];
    int pos = atomicAdd(&g_cursor[dst], 1);
    g_ssrc[pos] = src;
    g_sw[pos]   = ew[e];
}

// ---------------- agg[dst] = sum w * x[src]  (warp per dst) ------------
__global__ void agg_kernel(const float* __restrict__ x) {
    int gwarp = (blockIdx.x * 256 + threadIdx.x) >> 5;
    int lane  = threadIdx.x & 31;
    int s0 = g_offs[gwarp], s1 = g_offs[gwarp + 1];
    const float4* x4 = (const float4*)x;
    float4 acc = make_float4(0.f, 0.f, 0.f, 0.f);
    for (int e = s0; e < s1; e++) {
        int sn = g_ssrc[e];
        float w = g_sw[e];
        float4 v = x4[sn * 32 + lane];
        acc.x += w * v.x; acc.y += w * v.y; acc.z += w * v.z; acc.w += w * v.w;
    }
    ((float4*)g_agg)[gwarp * 32 + lane] = acc;
}

// ---------------- A_ext bf16 = [hi(agg|x) | lo(agg|x)] -------------------
__global__ void cvtA_bf(const float* __restrict__ x) {
    int idx = blockIdx.x * 256 + threadIdx.x;   // float4 id, 32768*64
    int row = idx >> 6;
    int c4  = (idx & 63) * 4;
    const float* src = (c4 < 128) ? &g_agg[(size_t)row * 128 + c4]
                                  : &x[(size_t)row * 128 + (c4 - 128)];
    float4 v = *(const float4*)src;
    __nv_bfloat16 hx = __float2bfloat16(v.x);
    __nv_bfloat16 hy = __float2bfloat16(v.y);
    __nv_bfloat16 hz = __float2bfloat16(v.z);
    __nv_bfloat16 hw = __float2bfloat16(v.w);
    __nv_bfloat16 lx = __float2bfloat16(v.x - __bfloat162float(hx));
    __nv_bfloat16 ly = __float2bfloat16(v.y - __bfloat162float(hy));
    __nv_bfloat16 lz = __float2bfloat16(v.z - __bfloat162float(hz));
    __nv_bfloat16 lw = __float2bfloat16(v.w - __bfloat162float(hw));
    __nv_bfloat16* dh = &g_Ab[(size_t)row * 512 + c4];
    __nv_bfloat16* dl = &g_Ab[(size_t)row * 512 + 256 + c4];
    dh[0] = hx; dh[1] = hy; dh[2] = hz; dh[3] = hw;
    dl[0] = lx; dl[1] = ly; dl[2] = lz; dl[3] = lw;
}

// ---------------- Bt[n][k] = [hi;hi;lo] of W = [W1;W2] -------------------
__global__ void cvtB_bf(const float* __restrict__ W1,
                        const float* __restrict__ W2) {
    int idx = blockIdx.x * 256 + threadIdx.x;   // 512*256
    int n = idx >> 8;
    int r = idx & 255;
    float v = (r < 128) ? W1[(size_t)r * 512 + n]
                        : W2[(size_t)(r - 128) * 512 + n];
    __nv_bfloat16 hi = __float2bfloat16(v);
    __nv_bfloat16 lo = __float2bfloat16(v - __bfloat162float(hi));
    g_Bt[(size_t)n * 768 + r]       = hi;
    g_Bt[(size_t)n * 768 + 256 + r] = hi;
    g_Bt[(size_t)n * 768 + 512 + r] = lo;
}

// ---------------- h = relu(A_ext @ Bt^T + b)  bf16 mma.sync GEMM ---------
// CTA tile 128(M)x128(N), BK=64 bf16 (128B SW128 rows), 12 stages,
// cp.async double buffer, ldmatrix fragment loads, m16n8k16.
// 8 warps: warp_m = wid&1 (64 rows), warp_n = wid>>1 (32 cols).
#define GB_SMEM 65536

__global__ __launch_bounds__(256) void gemm_h_bf(const float* __restrict__ bias) {
    extern __shared__ char dsm[];
    uint32_t base = smem_u32(dsm);
    uint32_t Ao[2] = { base,         base + 16384 };
    uint32_t Bo[2] = { base + 32768, base + 49152 };

    int tid  = threadIdx.x;
    int lane = tid & 31;
    int wid  = tid >> 5;
    int warp_m = wid & 1;
    int warp_n = wid >> 1;
    int bm = blockIdx.y * 128;
    int bn = blockIdx.x * 128;

    float cacc[4][4][4];
#pragma unroll
    for (int i = 0; i < 4; i++)
#pragma unroll
        for (int j = 0; j < 4; j++)
#pragma unroll
            for (int r = 0; r < 4; r++) cacc[i][j][r] = 0.f;

    auto load_stage = [&](int s, int buf) {
        int seg = s >> 2;
        int kA = ((s & 3) << 6) + (seg == 1 ? 256 : 0);  // hi, lo, hi
        int kB = s << 6;
#pragma unroll
        for (int t = 0; t < 4; t++) {
            int id  = tid + t * 256;               // 0..1023
            int r   = id >> 3;
            int c16 = id & 7;
            uint32_t off = SMEM_SWZ((uint32_t)(r * 128 + c16 * 16));
            cp16s(Ao[buf] + off, &g_Ab[(size_t)(bm + r) * 512 + kA + c16 * 8]);
        }
#pragma unroll
        for (int t = 0; t < 4; t++) {
            int id  = tid + t * 256;
            int r   = id >> 3;
            int c16 = id & 7;
            uint32_t off = SMEM_SWZ((uint32_t)(r * 128 + c16 * 16));
            cp16s(Bo[buf] + off, &g_Bt[(size_t)(bn + r) * 768 + kB + c16 * 8]);
        }
        asm volatile("cp.async.commit_group;" ::: "memory");
    };

    // per-lane ldmatrix row/col selectors
    int a_row  = warp_m * 64 + (lane & 15);        // + mi*16
    int a_csel = ((lane >> 4) & 1) * 16;           // byte offset within k16 chunk
    int b_row  = warp_n * 32 + (lane & 7);         // + ni*8
    int b_csel = (lane & 8) ? 16 : 0;

    load_stage(0, 0);

    for (int s = 0; s < 12; s++) {
        if (s < 11) {
            load_stage(s + 1, (s + 1) & 1);
            asm volatile("cp.async.wait_group 1;" ::: "memory");
        } else {
            asm volatile("cp.async.wait_group 0;" ::: "memory");
        }
        __syncthreads();

        uint32_t As = Ao[s & 1];
        uint32_t Bs = Bo[s & 1];
#pragma unroll
        for (int k = 0; k < 4; k++) {              // 4 x k16 per stage
            int kbA = k * 32 + a_csel;
            int kbB = k * 32 + b_csel;
            uint32_t a[4][4], b[4][2];
#pragma unroll
            for (int mi = 0; mi < 4; mi++) {
                uint32_t addr = As + SMEM_SWZ((uint32_t)((a_row + mi * 16) * 128 + kbA));
                ldsm4(a[mi], addr);
            }
#pragma unroll
            for (int ni = 0; ni < 4; ni++) {
                uint32_t addr = Bs + SMEM_SWZ((uint32_t)((b_row + ni * 8) * 128 + kbB));
                ldsm2(b[ni], addr);
            }
#pragma unroll
            for (int mi = 0; mi < 4; mi++)
#pragma unroll
                for (int ni = 0; ni < 4; ni++)
                    MMA_BF16(cacc[mi][ni], a[mi], b[ni]);
        }
        __syncthreads();
    }

    // epilogue: bias + relu
#pragma unroll
    for (int mi = 0; mi < 4; mi++) {
        int row0 = bm + warp_m * 64 + mi * 16 + (lane >> 2);
#pragma unroll
        for (int ni = 0; ni < 4; ni++) {
            int col = bn + warp_n * 32 + ni * 8 + 2 * (lane & 3);
            float b0 = bias[col], b1 = bias[col + 1];
            float2 v0, v1;
            v0.x = fmaxf(cacc[mi][ni][0] + b0, 0.f);
            v0.y = fmaxf(cacc[mi][ni][1] + b1, 0.f);
            v1.x = fmaxf(cacc[mi][ni][2] + b0, 0.f);
            v1.y = fmaxf(cacc[mi][ni][3] + b1, 0.f);
            *(float2*)&g_h[(size_t)row0 * HID + col]       = v0;
            *(float2*)&g_h[(size_t)(row0 + 8) * HID + col] = v1;
        }
    }
}

// ---------------- s_logits, softmax s, per-graph ss/den ----------------
__global__ void s_kernel(const float* __restrict__ Wp,
                         const float* __restrict__ bp,
                         float* __restrict__ dout) {
    __shared__ float red[8][4];
    int wip = threadIdx.x >> 5;
    int lane = threadIdx.x & 31;
    int node = blockIdx.x * 8 + wip;
    const float* hrow = g_h + (size_t)node * HID;
    float d0 = 0.f, d1 = 0.f;
    for (int k = lane; k < HID; k += 32) {
        float hv = hrow[k];
        d0 += hv * Wp[k * 2];
        d1 += hv * Wp[k * 2 + 1];
    }
    d0 = wred(d0); d1 = wred(d1);
    if (lane == 0) {
        d0 += bp[0]; d1 += bp[1];
        dout[OUT_SLOG + node * 2]     = d0;
        dout[OUT_SLOG + node * 2 + 1] = d1;
        float m = fmaxf(d0, d1);
        float e0 = expf(d0 - m), e1 = expf(d1 - m);
        float inv = 1.f / (e0 + e1);
        float s0 = e0 * inv, s1 = e1 * inv;
        g_s[node * 2] = s0; g_s[node * 2 + 1] = s1;
        float dn = g_d[node];
        red[wip][0] = s0 * s0;
        red[wip][1] = s0 * s1;
        red[wip][2] = s1 * s1;
        red[wip][3] = dn * (s0 * s0 + s1 * s1);
    }
    __syncthreads();
    if (threadIdx.x < 4) {
        int b = node >> 12;
        float t = 0.f;
#pragma unroll
        for (int w = 0; w < 8; w++) t += red[w][threadIdx.x];
        atomicAdd(&g_accum[b * 4 + threadIdx.x], t);
    }
}

// ---------------- out[b,c,f] = sum_n s[n,c]*h[n,f] ----------------------
__global__ void pool_kernel() {
    int b = blockIdx.x;
    int f = blockIdx.y * 128 + threadIdx.x;
    int ns = blockIdx.z;
    int nb = b * NLOC + ns * 512;
    float a0 = 0.f, a1 = 0.f;
    for (int n = 0; n < 512; n++) {
        int node = nb + n;
        float hv = g_h[(size_t)node * HID + f];
        a0 += g_s[node * 2] * hv;
        a1 += g_s[node * 2 + 1] * hv;
    }
    atomicAdd(&g_out[(b * 2 + 0) * HID + f], a0);
    atomicAdd(&g_out[(b * 2 + 1) * HID + f], a1);
}

// ---------------- out_adj[b,c,k] = sum_e s[src,c]*w*s[dst,k] ------------
__global__ void oa_kernel(const int* __restrict__ ei,
                          const float* __restrict__ ew) {
    __shared__ float red[8][4];
    int e = blockIdx.x * 256 + threadIdx.x;
    int src = ei[e];
    int dst = ei[NEDGE + e];
    float w = ew[e];
    float ss0 = g_s[src * 2], ss1 = g_s[src * 2 + 1];
    float sd0 = g_s[dst * 2], sd1 = g_s[dst * 2 + 1];
    float v00 = ss0 * w * sd0, v01 = ss0 * w * sd1;
    float v10 = ss1 * w * sd0, v11 = ss1 * w * sd1;
    v00 = wred(v00); v01 = wred(v01); v10 = wred(v10); v11 = wred(v11);
    int wip = threadIdx.x >> 5;
    if ((threadIdx.x & 31) == 0) {
        red[wip][0] = v00; red[wip][1] = v01; red[wip][2] = v10; red[wip][3] = v11;
    }
    __syncthreads();
    if (threadIdx.x < 4) {
        int b = src >> 12;
        float t = 0.f;
#pragma unroll
        for (int w2 = 0; w2 < 8; w2++) t += red[w2][threadIdx.x];
        atomicAdd(&g_oaraw[b * 4 + threadIdx.x], t);
    }
}

// ---------------- per-graph losses + out_adj normalization --------------
__global__ void finalize_kernel(float* __restrict__ dout) {
    int b = threadIdx.x;
    float mc = 0.f, ol = 0.f;
    if (b < NGR) {
        float a00 = g_oaraw[b * 4 + 0], a01 = g_oaraw[b * 4 + 1];
        float a10 = g_oaraw[b * 4 + 2], a11 = g_oaraw[b * 4 + 3];
        float num = a00 + a11;
        float den = g_accum[b * 4 + 3];
        mc = -(num / den);
        float ss00 = g_accum[b * 4 + 0], ss01 = g_accum[b * 4 + 1], ss11 = g_accum[b * 4 + 2];
        float nrm = sqrtf(ss00 * ss00 + 2.f * ss01 * ss01 + ss11 * ss11);
        const float q = 0.70710678118654752f;
        float n00 = ss00 / nrm - q, n01 = ss01 / nrm, n11 = ss11 / nrm - q;
        ol = sqrtf(n00 * n00 + 2.f * n01 * n01 + n11 * n11);
        float d2_0 = sqrtf(a01) + 1e-15f;
        float d2_1 = sqrtf(a10) + 1e-15f;
        float oa01 = a01 / (d2_0 * d2_1);
        float oa10 = a10 / (d2_1 * d2_0);
        g_oan[b * 4 + 0] = 0.f; g_oan[b * 4 + 1] = oa01;
        g_oan[b * 4 + 2] = oa10; g_oan[b * 4 + 3] = 0.f;
        dout[OUT_OA + b * 4 + 0] = 0.f;
        dout[OUT_OA + b * 4 + 1] = oa01;
        dout[OUT_OA + b * 4 + 2] = oa10;
        dout[OUT_OA + b * 4 + 3] = 0.f;
    }
    mc = wred(mc); ol = wred(ol);
    if (threadIdx.x == 0) {
        dout[OUT_MC] = mc / (float)NGR;
        dout[OUT_OL] = ol / (float)NGR;
    }
}

// ---------------- xm = mean_c(agg3@W_rel3 + b + out@W_root3) ------------
__global__ void xm_kernel(const float* __restrict__ Wrel3,
                          const float* __restrict__ brel3,
                          const float* __restrict__ Wroot3) {
    int b = blockIdx.x >> 1;
    int f = ((blockIdx.x & 1) << 8) + threadIdx.x;
    float oa01 = g_oan[b * 4 + 1], oa10 = g_oan[b * 4 + 2];
    const float* o0 = &g_out[(b * 2 + 0) * HID];
    const float* o1 = &g_out[(b * 2 + 1) * HID];
    float acc = 0.f;
    for (int k = 0; k < HID; k++) {
        float u = oa10 * o1[k] + oa01 * o0[k];
        float v = o0[k] + o1[k];
        acc += u * Wrel3[k * HID + f] + v * Wroot3[k * HID + f];
    }
    g_xm[b * HID + f] = 0.5f * acc + brel3[f];
}

// ---------------- h2 = relu(xm @ W_lin1 + b) ----------------------------
__global__ void h2_kernel(const float* __restrict__ Wlin1,
                          const float* __restrict__ blin1) {
    int b = blockIdx.x >> 1;
    int f = ((blockIdx.x & 1) << 8) + threadIdx.x;
    float acc = 0.f;
    for (int k = 0; k < HID; k++)
        acc += g_xm[b * HID + k] * Wlin1[k * HID + f];
    g_h2[b * HID + f] = fmaxf(acc + blin1[f], 0.f);
}

// ---------------- logits + log_softmax ----------------------------------
__global__ void logits_kernel(const float* __restrict__ Wlin2,
                              const float* __restrict__ blin2,
                              float* __restrict__ dout) {
    __shared__ float lg[10];
    int b = blockIdx.x;
    int o = threadIdx.x >> 5;
    int lane = threadIdx.x & 31;
    float acc = 0.f;
    for (int k = lane; k < HID; k += 32)
        acc += g_h2[b * HID + k] * Wlin2[k * 10 + o];
    acc = wred(acc);
    if (lane == 0) lg[o] = acc + blin2[o];
    __syncthreads();
    if (threadIdx.x == 0) {
        float m = lg[0];
#pragma unroll
        for (int i = 1; i < 10; i++) m = fmaxf(m, lg[i]);
        float s = 0.f;
#pragma unroll
        for (int i = 0; i < 10; i++) s += expf(lg[i] - m);
        float lse = logf(s) + m;
#pragma unroll
        for (int i = 0; i < 10; i++) dout[b * 10 + i] = lg[i] - lse;
    }
}

extern "C" void kernel_launch(void* const* d_in, const int* in_sizes, int n_in,
                              void* d_out, int out_size) {
    const float* x       = (const float*)d_in[0];
    const int*   ei      = (const int*)d_in[1];   // int32 (JAX x64 disabled)
    const float* ew      = (const float*)d_in[3];
    const float* W_rel1  = (const float*)d_in[4];
    const float* b_rel1  = (const float*)d_in[5];
    const float* W_root1 = (const float*)d_in[6];
    const float* W_pool  = (const float*)d_in[7];
    const float* b_pool  = (const float*)d_in[8];
    const float* W_rel3  = (const float*)d_in[9];
    const float* b_rel3  = (const float*)d_in[10];
    const float* W_root3 = (const float*)d_in[11];
    const float* W_lin1  = (const float*)d_in[12];
    const float* b_lin1  = (const float*)d_in[13];
    const float* W_lin2  = (const float*)d_in[14];
    const float* b_lin2  = (const float*)d_in[15];
    float* out = (float*)d_out;

    static int smem_set = 0;
    if (!smem_set) {
        cudaFuncSetAttribute(gemm_h_bf, cudaFuncAttributeMaxDynamicSharedMemorySize,
                             GB_SMEM);
        smem_set = 1;
    }

    zero_kernel<<<129, 256>>>();
    count_kernel<<<NEDGE / 256, 256>>>(ei, ew);
    scan_kernel<<<1, 1024>>>();
    scatter_kernel<<<NEDGE / 256, 256>>>(ei, ew);
    agg_kernel<<<NNODE / 8, 256>>>(x);
    cvtA_bf<<<NNODE * 64 / 256, 256>>>(x);
    cvtB_bf<<<512, 256>>>(W_rel1, W_root1);
    gemm_h_bf<<<dim3(HID / 128, NNODE / 128), 256, GB_SMEM>>>(b_rel1);
    s_kernel<<<NNODE / 8, 256>>>(W_pool, b_pool, out);
    pool_kernel<<<dim3(NGR, 4, 8), 128>>>();
    oa_kernel<<<NEDGE / 256, 256>>>(ei, ew);
    finalize_kernel<<<1, 32>>>(out);
    xm_kernel<<<16, 256>>>(W_rel3, b_rel3, W_root3);
    h2_kernel<<<16, 256>>>(W_lin1, b_lin1);
    logits_kernel<<<8, 320>>>(W_lin2, b_lin2, out);
}

// round 7
// speedup vs baseline: 1.6252x; 1.1421x over previous
#include <cuda_runtime.h>
#include <cuda_bf16.h>
#include <math.h>
#include <stdint.h>

#define NEDGE 524288
#define NNODE 32768
#define NGR   8
#define NLOC  4096
#define FIN   128
#define HID   512

#define OUT_MC    80
#define OUT_OL    81
#define OUT_SLOG  82
#define OUT_OA    65618

// ---- scratch ----
__device__ __nv_bfloat16  g_Ab[NNODE * 512];     // [hi(agg|x) | lo(agg|x)]
__device__ __nv_bfloat16  g_Bt[512 * 768];       // Bt[n][k]: k = [hi|hi|lo] of W=[W1;W2]
__device__ float g_h[NNODE * HID];
__device__ float g_s[NNODE * 2];
__device__ int   g_cnt[NNODE + 1];
__device__ int   g_offs[NNODE + 1];
__device__ int   g_cursor[NNODE];
__device__ int   g_ssrc[NEDGE];
__device__ float g_sw[NEDGE];
__device__ float g_d[NNODE];
__device__ float g_accum[NGR * 4];
__device__ float g_oaraw[NGR * 4];
__device__ float g_oan[NGR * 4];
__device__ float g_out[NGR * 2 * HID];
__device__ float g_xm[NGR * HID];
__device__ float g_h2[NGR * HID];

__device__ __forceinline__ float wredx(float v) {
#pragma unroll
    for (int o = 16; o; o >>= 1) v += __shfl_xor_sync(0xffffffffu, v, o);
    return v;
}

#define SMEM_SWZ(o) ((o) ^ (((o) >> 3) & 0x70))

__device__ __forceinline__ uint32_t smem_u32(const void* p) {
    return (uint32_t)__cvta_generic_to_shared(p);
}
__device__ __forceinline__ void cp16s(uint32_t saddr, const void* g) {
    asm volatile("cp.async.cg.shared.global [%0], [%1], 16;"
                 :: "r"(saddr), "l"(g) : "memory");
}
__device__ __forceinline__ void ldsm4(uint32_t* r, uint32_t a) {
    asm volatile("ldmatrix.sync.aligned.m8n8.x4.shared.b16 {%0,%1,%2,%3}, [%4];"
                 : "=r"(r[0]), "=r"(r[1]), "=r"(r[2]), "=r"(r[3]) : "r"(a));
}
__device__ __forceinline__ void ldsm2(uint32_t* r, uint32_t a) {
    asm volatile("ldmatrix.sync.aligned.m8n8.x2.shared.b16 {%0,%1}, [%2];"
                 : "=r"(r[0]), "=r"(r[1]) : "r"(a));
}
#define MMA_BF16(d, a, b)                                                     \
    asm volatile(                                                             \
        "mma.sync.aligned.m16n8k16.row.col.f32.bf16.bf16.f32 "                \
        "{%0,%1,%2,%3},{%4,%5,%6,%7},{%8,%9},{%0,%1,%2,%3};"                  \
        : "+f"((d)[0]), "+f"((d)[1]), "+f"((d)[2]), "+f"((d)[3])              \
        : "r"((a)[0]), "r"((a)[1]), "r"((a)[2]), "r"((a)[3]),                 \
          "r"((b)[0]), "r"((b)[1]))

// ---------------- zero scratch ----------------
__global__ void zero_kernel() {
    int i = blockIdx.x * 256 + threadIdx.x;
    if (i < NNODE + 1) g_cnt[i] = 0;
    if (i < NNODE)     g_d[i] = 0.f;
    if (i < NGR * 2 * HID) g_out[i] = 0.f;
    if (i < NGR * 4) { g_accum[i] = 0.f; g_oaraw[i] = 0.f; }
}

// ---------------- count by dst + degree by src ----------------
__global__ void count_kernel(const int* __restrict__ ei,
                             const float* __restrict__ ew) {
    int e = blockIdx.x * 256 + threadIdx.x;
    if (e >= NEDGE) return;
    int src = ei[e];
    int dst = ei[NEDGE + e];
    atomicAdd(&g_cnt[dst], 1);
    atomicAdd(&g_d[src], ew[e]);
}

// ---------------- exclusive scan (1 block, 1024 thr) ----------------
__global__ void scan_kernel() {
    __shared__ int sm[1024];
    int tid = threadIdx.x;
    int base = tid * 32;
    int sum = 0;
#pragma unroll
    for (int i = 0; i < 32; i++) sum += g_cnt[base + i];
    sm[tid] = sum;
    __syncthreads();
    for (int o = 1; o < 1024; o <<= 1) {
        int v = (tid >= o) ? sm[tid - o] : 0;
        __syncthreads();
        sm[tid] += v;
        __syncthreads();
    }
    int run = sm[tid] - sum;
#pragma unroll
    for (int i = 0; i < 32; i++) {
        int c = g_cnt[base + i];
        g_offs[base + i] = run;
        g_cursor[base + i] = run;
        run += c;
    }
    if (tid == 1023) g_offs[NNODE] = run;
}

// ---------------- scatter edges sorted by dst ----------------
__global__ void scatter_kernel(const int* __restrict__ ei,
                               const float* __restrict__ ew) {
    int e = blockIdx.x * 256 + threadIdx.x;
    if (e >= NEDGE) return;
    int src = ei[e];
    int dst = ei[NEDGE + e];
    int pos = atomicAdd(&g_cursor[dst], 1);
    g_ssrc[pos] = src;
    g_sw[pos]   = ew[e];
}

// ---------------- agg -> bf16 hi/lo directly (warp per dst) ------------
__global__ void agg_kernel(const float* __restrict__ x) {
    int gwarp = (blockIdx.x * 256 + threadIdx.x) >> 5;
    int lane  = threadIdx.x & 31;
    int s0 = g_offs[gwarp], s1 = g_offs[gwarp + 1];
    const float4* x4 = (const float4*)x;
    float4 acc = make_float4(0.f, 0.f, 0.f, 0.f);
    int e = s0;
    for (; e + 4 <= s1; e += 4) {
        int sn0 = g_ssrc[e],     sn1 = g_ssrc[e + 1];
        int sn2 = g_ssrc[e + 2], sn3 = g_ssrc[e + 3];
        float w0 = g_sw[e],     w1 = g_sw[e + 1];
        float w2 = g_sw[e + 2], w3 = g_sw[e + 3];
        float4 v0 = x4[sn0 * 32 + lane];
        float4 v1 = x4[sn1 * 32 + lane];
        float4 v2 = x4[sn2 * 32 + lane];
        float4 v3 = x4[sn3 * 32 + lane];
        acc.x += w0 * v0.x; acc.y += w0 * v0.y; acc.z += w0 * v0.z; acc.w += w0 * v0.w;
        acc.x += w1 * v1.x; acc.y += w1 * v1.y; acc.z += w1 * v1.z; acc.w += w1 * v1.w;
        acc.x += w2 * v2.x; acc.y += w2 * v2.y; acc.z += w2 * v2.z; acc.w += w2 * v2.w;
        acc.x += w3 * v3.x; acc.y += w3 * v3.y; acc.z += w3 * v3.z; acc.w += w3 * v3.w;
    }
    for (; e < s1; e++) {
        int sn = g_ssrc[e];
        float w = g_sw[e];
        float4 v = x4[sn * 32 + lane];
        acc.x += w * v.x; acc.y += w * v.y; acc.z += w * v.z; acc.w += w * v.w;
    }
    // split to bf16 hi/lo; agg occupies hi[0..127], lo[256..383] of A_ext row
    __nv_bfloat16 h[4], l[4];
    float vv[4] = { acc.x, acc.y, acc.z, acc.w };
#pragma unroll
    for (int j = 0; j < 4; j++) {
        h[j] = __float2bfloat16(vv[j]);
        l[j] = __float2bfloat16(vv[j] - __bfloat162float(h[j]));
    }
    size_t rb = (size_t)gwarp * 512 + lane * 4;
    *(uint2*)&g_Ab[rb]       = *(uint2*)h;
    *(uint2*)&g_Ab[rb + 256] = *(uint2*)l;
}

// ---------------- x half of A_ext: hi[128..255], lo[384..511] ------------
__global__ void cvtX_bf(const float* __restrict__ x) {
    int idx = blockIdx.x * 256 + threadIdx.x;   // float4 id, 32768*32
    int row = idx >> 5;
    int c4  = (idx & 31) * 4;
    float4 v = *(const float4*)&x[(size_t)row * 128 + c4];
    __nv_bfloat16 h[4], l[4];
    float vv[4] = { v.x, v.y, v.z, v.w };
#pragma unroll
    for (int j = 0; j < 4; j++) {
        h[j] = __float2bfloat16(vv[j]);
        l[j] = __float2bfloat16(vv[j] - __bfloat162float(h[j]));
    }
    size_t rb = (size_t)row * 512;
    *(uint2*)&g_Ab[rb + 128 + c4] = *(uint2*)h;
    *(uint2*)&g_Ab[rb + 384 + c4] = *(uint2*)l;
}

// ---------------- Bt[n][k] = [hi;hi;lo] of W = [W1;W2] -------------------
__global__ void cvtB_bf(const float* __restrict__ W1,
                        const float* __restrict__ W2) {
    int idx = blockIdx.x * 256 + threadIdx.x;   // 512*256
    int n = idx >> 8;
    int r = idx & 255;
    float v = (r < 128) ? W1[(size_t)r * 512 + n]
                        : W2[(size_t)(r - 128) * 512 + n];
    __nv_bfloat16 hi = __float2bfloat16(v);
    __nv_bfloat16 lo = __float2bfloat16(v - __bfloat162float(hi));
    g_Bt[(size_t)n * 768 + r]       = hi;
    g_Bt[(size_t)n * 768 + 256 + r] = hi;
    g_Bt[(size_t)n * 768 + 512 + r] = lo;
}

// ---------------- h = relu(A_ext @ Bt^T + b)  bf16 mma.sync GEMM ---------
// 128x128 tile, BK=64 (128B SW128 rows), 12 stages, 3-stage cp.async ring.
#define GB_SMEM 98304

__global__ __launch_bounds__(256) void gemm_h_bf(const float* __restrict__ bias) {
    extern __shared__ char dsm[];
    uint32_t base = smem_u32(dsm);
    uint32_t Ao[3] = { base,         base + 16384, base + 32768 };
    uint32_t Bo[3] = { base + 49152, base + 65536, base + 81920 };

    int tid  = threadIdx.x;
    int lane = tid & 31;
    int wid  = tid >> 5;
    int warp_m = wid & 1;
    int warp_n = wid >> 1;
    int bm = blockIdx.y * 128;
    int bn = blockIdx.x * 128;

    float cacc[4][4][4];
#pragma unroll
    for (int i = 0; i < 4; i++)
#pragma unroll
        for (int j = 0; j < 4; j++)
#pragma unroll
            for (int r = 0; r < 4; r++) cacc[i][j][r] = 0.f;

    auto load_stage = [&](int s, int buf) {
        int seg = s >> 2;
        int kA = ((s & 3) << 6) + (seg == 1 ? 256 : 0);  // hi, lo, hi
        int kB = s << 6;
#pragma unroll
        for (int t = 0; t < 4; t++) {
            int id  = tid + t * 256;
            int r   = id >> 3;
            int c16 = id & 7;
            uint32_t off = SMEM_SWZ((uint32_t)(r * 128 + c16 * 16));
            cp16s(Ao[buf] + off, &g_Ab[(size_t)(bm + r) * 512 + kA + c16 * 8]);
        }
#pragma unroll
        for (int t = 0; t < 4; t++) {
            int id  = tid + t * 256;
            int r   = id >> 3;
            int c16 = id & 7;
            uint32_t off = SMEM_SWZ((uint32_t)(r * 128 + c16 * 16));
            cp16s(Bo[buf] + off, &g_Bt[(size_t)(bn + r) * 768 + kB + c16 * 8]);
        }
        asm volatile("cp.async.commit_group;" ::: "memory");
    };

    int a_row  = warp_m * 64 + (lane & 15);
    int a_csel = ((lane >> 4) & 1) * 16;
    int b_row  = warp_n * 32 + (lane & 7);
    int b_csel = (lane & 8) ? 16 : 0;

    load_stage(0, 0);
    load_stage(1, 1);

    for (int s = 0; s < 12; s++) {
        if (s + 2 < 12) {
            load_stage(s + 2, (s + 2) % 3);
            asm volatile("cp.async.wait_group 2;" ::: "memory");
        } else if (s + 1 < 12) {
            asm volatile("cp.async.wait_group 1;" ::: "memory");
        } else {
            asm volatile("cp.async.wait_group 0;" ::: "memory");
        }
        __syncthreads();

        uint32_t As = Ao[s % 3];
        uint32_t Bs = Bo[s % 3];
#pragma unroll
        for (int k = 0; k < 4; k++) {
            int kbA = k * 32 + a_csel;
            int kbB = k * 32 + b_csel;
            uint32_t a[4][4], b[4][2];
#pragma unroll
            for (int mi = 0; mi < 4; mi++) {
                uint32_t addr = As + SMEM_SWZ((uint32_t)((a_row + mi * 16) * 128 + kbA));
                ldsm4(a[mi], addr);
            }
#pragma unroll
            for (int ni = 0; ni < 4; ni++) {
                uint32_t addr = Bs + SMEM_SWZ((uint32_t)((b_row + ni * 8) * 128 + kbB));
                ldsm2(b[ni], addr);
            }
#pragma unroll
            for (int mi = 0; mi < 4; mi++)
#pragma unroll
                for (int ni = 0; ni < 4; ni++)
                    MMA_BF16(cacc[mi][ni], a[mi], b[ni]);
        }
        __syncthreads();
    }

    // epilogue: bias + relu
#pragma unroll
    for (int mi = 0; mi < 4; mi++) {
        int row0 = bm + warp_m * 64 + mi * 16 + (lane >> 2);
#pragma unroll
        for (int ni = 0; ni < 4; ni++) {
            int col = bn + warp_n * 32 + ni * 8 + 2 * (lane & 3);
            float b0 = bias[col], b1 = bias[col + 1];
            float2 v0, v1;
            v0.x = fmaxf(cacc[mi][ni][0] + b0, 0.f);
            v0.y = fmaxf(cacc[mi][ni][1] + b1, 0.f);
            v1.x = fmaxf(cacc[mi][ni][2] + b0, 0.f);
            v1.y = fmaxf(cacc[mi][ni][3] + b1, 0.f);
            *(float2*)&g_h[(size_t)row0 * HID + col]       = v0;
            *(float2*)&g_h[(size_t)(row0 + 8) * HID + col] = v1;
        }
    }
}

// ------- fused: s_logits + softmax + ss/den + pooled features ------------
// 1024 blocks x 256 thr; warp handles 4 nodes; block = 32 nodes (same graph).
__global__ __launch_bounds__(256) void s_pool_kernel(const float* __restrict__ Wp,
                                                     const float* __restrict__ bp,
                                                     float* __restrict__ dout) {
    __shared__ float psm[8][1024];
    __shared__ float red[8][4];
    int tid  = threadIdx.x;
    int wip  = tid >> 5;
    int lane = tid & 31;

    // cache W_pool columns for this lane's 16 features
    float wp0[16], wp1[16];
#pragma unroll
    for (int i = 0; i < 16; i++) {
        int k = lane + 32 * i;
        float2 w2 = *(const float2*)&Wp[k * 2];
        wp0[i] = w2.x; wp1[i] = w2.y;
    }
    float bp0 = bp[0], bp1 = bp[1];

    float pa0[16], pa1[16];
#pragma unroll
    for (int i = 0; i < 16; i++) { pa0[i] = 0.f; pa1[i] = 0.f; }
    float ss00 = 0.f, ss01 = 0.f, ss11 = 0.f, den = 0.f;

    int nbase = blockIdx.x * 32 + wip * 4;
#pragma unroll
    for (int nn = 0; nn < 4; nn++) {
        int node = nbase + nn;
        const float* hrow = g_h + (size_t)node * HID;
        float hv[16];
        float d0 = 0.f, d1 = 0.f;
#pragma unroll
        for (int i = 0; i < 16; i++) {
            hv[i] = hrow[lane + 32 * i];
            d0 += hv[i] * wp0[i];
            d1 += hv[i] * wp1[i];
        }
        d0 = wredx(d0) + bp0;
        d1 = wredx(d1) + bp1;
        float m = fmaxf(d0, d1);
        float e0 = expf(d0 - m), e1 = expf(d1 - m);
        float inv = 1.f / (e0 + e1);
        float s0 = e0 * inv, s1 = e1 * inv;
        if (lane == 0) {
            dout[OUT_SLOG + node * 2]     = d0;
            dout[OUT_SLOG + node * 2 + 1] = d1;
            g_s[node * 2] = s0; g_s[node * 2 + 1] = s1;
            float dn = g_d[node];
            ss00 += s0 * s0; ss01 += s0 * s1; ss11 += s1 * s1;
            den  += dn * (s0 * s0 + s1 * s1);
        }
#pragma unroll
        for (int i = 0; i < 16; i++) {
            pa0[i] += s0 * hv[i];
            pa1[i] += s1 * hv[i];
        }
    }
#pragma unroll
    for (int i = 0; i < 16; i++) {
        psm[wip][lane + 32 * i]       = pa0[i];
        psm[wip][512 + lane + 32 * i] = pa1[i];
    }
    if (lane == 0) {
        red[wip][0] = ss00; red[wip][1] = ss01; red[wip][2] = ss11; red[wip][3] = den;
    }
    __syncthreads();

    int b = nbase >> 12;
    for (int f = tid; f < 1024; f += 256) {
        float t = 0.f;
#pragma unroll
        for (int w = 0; w < 8; w++) t += psm[w][f];
        atomicAdd(&g_out[b * 1024 + f], t);
    }
    if (tid < 4) {
        float t = 0.f;
#pragma unroll
        for (int w = 0; w < 8; w++) t += red[w][tid];
        atomicAdd(&g_accum[b * 4 + tid], t);
    }
}

// ---------------- out_adj[b,c,k] = sum_e s[src,c]*w*s[dst,k] ------------
__global__ void oa_kernel(const int* __restrict__ ei,
                          const float* __restrict__ ew) {
    __shared__ float red[8][4];
    int e = blockIdx.x * 256 + threadIdx.x;
    int src = ei[e];
    int dst = ei[NEDGE + e];
    float w = ew[e];
    float ss0 = g_s[src * 2], ss1 = g_s[src * 2 + 1];
    float sd0 = g_s[dst * 2], sd1 = g_s[dst * 2 + 1];
    float v00 = ss0 * w * sd0, v01 = ss0 * w * sd1;
    float v10 = ss1 * w * sd0, v11 = ss1 * w * sd1;
    v00 = wredx(v00); v01 = wredx(v01); v10 = wredx(v10); v11 = wredx(v11);
    int wip = threadIdx.x >> 5;
    if ((threadIdx.x & 31) == 0) {
        red[wip][0] = v00; red[wip][1] = v01; red[wip][2] = v10; red[wip][3] = v11;
    }
    __syncthreads();
    if (threadIdx.x < 4) {
        int b = src >> 12;
        float t = 0.f;
#pragma unroll
        for (int w2 = 0; w2 < 8; w2++) t += red[w2][threadIdx.x];
        atomicAdd(&g_oaraw[b * 4 + threadIdx.x], t);
    }
}

// ---------------- per-graph losses + out_adj normalization --------------
__global__ void finalize_kernel(float* __restrict__ dout) {
    int b = threadIdx.x;
    float mc = 0.f, ol = 0.f;
    if (b < NGR) {
        float a00 = g_oaraw[b * 4 + 0], a01 = g_oaraw[b * 4 + 1];
        float a10 = g_oaraw[b * 4 + 2], a11 = g_oaraw[b * 4 + 3];
        float num = a00 + a11;
        float den = g_accum[b * 4 + 3];
        mc = -(num / den);
        float ss00 = g_accum[b * 4 + 0], ss01 = g_accum[b * 4 + 1], ss11 = g_accum[b * 4 + 2];
        float nrm = sqrtf(ss00 * ss00 + 2.f * ss01 * ss01 + ss11 * ss11);
        const float q = 0.70710678118654752f;
        float n00 = ss00 / nrm - q, n01 = ss01 / nrm, n11 = ss11 / nrm - q;
        ol = sqrtf(n00 * n00 + 2.f * n01 * n01 + n11 * n11);
        float d2_0 = sqrtf(a01) + 1e-15f;
        float d2_1 = sqrtf(a10) + 1e-15f;
        float oa01 = a01 / (d2_0 * d2_1);
        float oa10 = a10 / (d2_1 * d2_0);
        g_oan[b * 4 + 0] = 0.f; g_oan[b * 4 + 1] = oa01;
        g_oan[b * 4 + 2] = oa10; g_oan[b * 4 + 3] = 0.f;
        dout[OUT_OA + b * 4 + 0] = 0.f;
        dout[OUT_OA + b * 4 + 1] = oa01;
        dout[OUT_OA + b * 4 + 2] = oa10;
        dout[OUT_OA + b * 4 + 3] = 0.f;
    }
#pragma unroll
    for (int o = 16; o; o >>= 1) { mc += __shfl_xor_sync(0xffffffffu, mc, o);
                                   ol += __shfl_xor_sync(0xffffffffu, ol, o); }
    if (threadIdx.x == 0) {
        dout[OUT_MC] = mc / (float)NGR;
        dout[OUT_OL] = ol / (float)NGR;
    }
}

// ---------------- xm = mean_c(agg3@W_rel3 + b + out@W_root3) ------------
__global__ void xm_kernel(const float* __restrict__ Wrel3,
                          const float* __restrict__ brel3,
                          const float* __restrict__ Wroot3) {
    int b = blockIdx.x >> 1;
    int f = ((blockIdx.x & 1) << 8) + threadIdx.x;
    float oa01 = g_oan[b * 4 + 1], oa10 = g_oan[b * 4 + 2];
    const float* o0 = &g_out[(b * 2 + 0) * HID];
    const float* o1 = &g_out[(b * 2 + 1) * HID];
    float acc = 0.f;
    for (int k = 0; k < HID; k++) {
        float u = oa10 * o1[k] + oa01 * o0[k];
        float v = o0[k] + o1[k];
        acc += u * Wrel3[k * HID + f] + v * Wroot3[k * HID + f];
    }
    g_xm[b * HID + f] = 0.5f * acc + brel3[f];
}

// ---------------- h2 = relu(xm @ W_lin1 + b) ----------------------------
__global__ void h2_kernel(const float* __restrict__ Wlin1,
                          const float* __restrict__ blin1) {
    int b = blockIdx.x >> 1;
    int f = ((blockIdx.x & 1) << 8) + threadIdx.x;
    float acc = 0.f;
    for (int k = 0; k < HID; k++)
        acc += g_xm[b * HID + k] * Wlin1[k * HID + f];
    g_h2[b * HID + f] = fmaxf(acc + blin1[f], 0.f);
}

// ---------------- logits + log_softmax ----------------------------------
__global__ void logits_kernel(const float* __restrict__ Wlin2,
                              const float* __restrict__ blin2,
                              float* __restrict__ dout) {
    __shared__ float lg[10];
    int b = blockIdx.x;
    int o = threadIdx.x >> 5;
    int lane = threadIdx.x & 31;
    float acc = 0.f;
    for (int k = lane; k < HID; k += 32)
        acc += g_h2[b * HID + k] * Wlin2[k * 10 + o];
    acc = wredx(acc);
    if (lane == 0) lg[o] = acc + blin2[o];
    __syncthreads();
    if (threadIdx.x == 0) {
        float m = lg[0];
#pragma unroll
        for (int i = 1; i < 10; i++) m = fmaxf(m, lg[i]);
        float s = 0.f;
#pragma unroll
        for (int i = 0; i < 10; i++) s += expf(lg[i] - m);
        float lse = logf(s) + m;
#pragma unroll
        for (int i = 0; i < 10; i++) dout[b * 10 + i] = lg[i] - lse;
    }
}

extern "C" void kernel_launch(void* const* d_in, const int* in_sizes, int n_in,
                              void* d_out, int out_size) {
    const float* x       = (const float*)d_in[0];
    const int*   ei      = (const int*)d_in[1];   // int32 (JAX x64 disabled)
    const float* ew      = (const float*)d_in[3];
    const float* W_rel1  = (const float*)d_in[4];
    const float* b_rel1  = (const float*)d_in[5];
    const float* W_root1 = (const float*)d_in[6];
    const float* W_pool  = (const float*)d_in[7];
    const float* b_pool  = (const float*)d_in[8];
    const float* W_rel3  = (const float*)d_in[9];
    const float* b_rel3  = (const float*)d_in[10];
    const float* W_root3 = (const float*)d_in[11];
    const float* W_lin1  = (const float*)d_in[12];
    const float* b_lin1  = (const float*)d_in[13];
    const float* W_lin2  = (const float*)d_in[14];
    const float* b_lin2  = (const float*)d_in[15];
    float* out = (float*)d_out;

    static int smem_set = 0;
    if (!smem_set) {
        cudaFuncSetAttribute(gemm_h_bf, cudaFuncAttributeMaxDynamicSharedMemorySize,
                             GB_SMEM);
        smem_set = 1;
    }

    zero_kernel<<<129, 256>>>();
    count_kernel<<<NEDGE / 256, 256>>>(ei, ew);
    scan_kernel<<<1, 1024>>>();
    scatter_kernel<<<NEDGE / 256, 256>>>(ei, ew);
    agg_kernel<<<NNODE / 8, 256>>>(x);
    cvtX_bf<<<NNODE * 32 / 256, 256>>>(x);
    cvtB_bf<<<512, 256>>>(W_rel1, W_root1);
    gemm_h_bf<<<dim3(HID / 128, NNODE / 128), 256, GB_SMEM>>>(b_rel1);
    s_pool_kernel<<<NNODE / 32, 256>>>(W_pool, b_pool, out);
    oa_kernel<<<NEDGE / 256, 256>>>(ei, ew);
    finalize_kernel<<<1, 32>>>(out);
    xm_kernel<<<16, 256>>>(W_rel3, b_rel3, W_root3);
    h2_kernel<<<16, 256>>>(W_lin1, b_lin1);
    logits_kernel<<<8, 320>>>(W_lin2, b_lin2, out);
}